// round 10
// baseline (speedup 1.0000x reference)
#include <cuda_runtime.h>
#include <cuda_fp16.h>
#include <cstdint>

// ---------------- problem constants ----------------
#define B_SZ 8
#define L_SZ 4096
#define ML (B_SZ * L_SZ)        // 32768
#define DM 280
#define DI 560
#define DS 16
#define DTR 18
#define NPROJ (DTR + 2 * DS)    // 50
#define TWO_DI (2 * DI)         // 1120
#define NCH 64
#define CHL (L_SZ / NCH)        // 64

typedef __half f16;

// ---------------- scratch (static device memory; no allocs) ----------------
__device__ float g_z[(size_t)ML * DI];
__device__ float g_proj[(size_t)ML * NPROJ];
__device__ float g_hend[(size_t)NCH * B_SZ * DI * DS];
__device__ float g_hinit[(size_t)NCH * B_SZ * DI * DS];
__device__ float g_sdt[(size_t)NCH * B_SZ * DI];

__device__ __align__(256) f16 g_xh[(size_t)ML * DM];
__device__ __align__(256) f16 g_xl[(size_t)ML * DM];
__device__ __align__(256) f16 g_xch[(size_t)ML * DI];
__device__ __align__(256) f16 g_xcl[(size_t)ML * DI];
__device__ __align__(256) f16 g_yh[(size_t)ML * DI];
__device__ __align__(256) f16 g_yl[(size_t)ML * DI];
__device__ __align__(256) f16 g_wih[(size_t)3 * TWO_DI * DM];
__device__ __align__(256) f16 g_wxh[(size_t)3 * NPROJ * DI];
__device__ __align__(256) f16 g_wxl[(size_t)3 * NPROJ * DI];
__device__ __align__(256) f16 g_woh[(size_t)3 * DM * DI];

// ---------------- PTX helpers (sm_100 base ISA only: HMMA/ldmatrix/cp.async) ----
__device__ __forceinline__ uint32_t smem_u32(const void* p) {
    uint32_t a;
    asm("{ .reg .u64 t; cvta.to.shared.u64 t, %1; cvt.u32.u64 %0, t; }" : "=r"(a) : "l"(p));
    return a;
}
__device__ __forceinline__ void cp16(uint32_t dst, const void* src, bool pred) {
    int sz = pred ? 16 : 0;
    asm volatile("cp.async.cg.shared.global [%0], [%1], 16, %2;"
                 :: "r"(dst), "l"(src), "r"(sz) : "memory");
}
__device__ __forceinline__ void cp_commit() {
    asm volatile("cp.async.commit_group;" ::: "memory");
}
template <int N>
__device__ __forceinline__ void cp_wait() {
    asm volatile("cp.async.wait_group %0;" :: "n"(N) : "memory");
}
__device__ __forceinline__ void ldm_x4(uint32_t addr, uint32_t* r) {
    asm volatile("ldmatrix.sync.aligned.m8n8.x4.shared.b16 {%0,%1,%2,%3}, [%4];"
                 : "=r"(r[0]), "=r"(r[1]), "=r"(r[2]), "=r"(r[3]) : "r"(addr));
}
__device__ __forceinline__ void mma16816(float* c, const uint32_t* a, const uint32_t* b) {
    asm volatile("mma.sync.aligned.m16n8k16.row.col.f32.f16.f16.f32 "
                 "{%0,%1,%2,%3}, {%4,%5,%6,%7}, {%8,%9}, {%0,%1,%2,%3};"
                 : "+f"(c[0]), "+f"(c[1]), "+f"(c[2]), "+f"(c[3])
                 : "r"(a[0]), "r"(a[1]), "r"(a[2]), "r"(a[3]), "r"(b[0]), "r"(b[1]));
}

// ---------------- HMMA fp16 GEMM: C[M,N] = A[M,K] * W[N,K]^T ----------------
// TERMS=2: D = AhWh + AlWh (W single fp16). TERMS=3: + AhWl (W split).
// CTA tile 128 x BN x 32. 8 warps. 3-stage cp.async pipeline, ONE sync per chunk.
// Optional fused epilogue (cvw != null): causal conv(4)+silu+fp16-split on cols<DI,
// fp32 z passthrough on cols in [DI, 2*DI).
#define GBK 32
#define LDA 40                   // f16 elems/row (32 + 8 pad); row stride 80B
#define STAGES 3
#define EPL 132                  // fp32 epilogue tile stride

template <int BN, int TERMS>
__global__ __launch_bounds__(256) void gemm_f16s(
    const f16* __restrict__ Ah, const f16* __restrict__ Al,
    const f16* __restrict__ Wh, const f16* __restrict__ Wl,
    float* __restrict__ C, f16* __restrict__ Ch, f16* __restrict__ Cl,
    const float* __restrict__ cvw, const float* __restrict__ cvb,
    f16* __restrict__ cXh, f16* __restrict__ cXl, float* __restrict__ cZ,
    int N, int K)
{
    constexpr int NWN = BN / 32;            // warps along N
    constexpr int MF = (128 / (8 / NWN)) / 16; // m-frags per warp
    constexpr int SM_AH = 0;
    constexpr int SM_AL = 10240;
    constexpr int SM_W  = 20480;
    constexpr int SM_WL = 20480 + BN * 80;
    constexpr int STAGE = 20480 + BN * 80 * (TERMS - 1);

    extern __shared__ char smem[];
    uint32_t sb = smem_u32(smem);
    int tid = threadIdx.x;
    int lane = tid & 31, wid = tid >> 5;
    int wm = wid / NWN, wn = wid % NWN;
    int bm = blockIdx.y * 128, bn = blockIdx.x * BN;
    int nch = (K + GBK - 1) / GBK;

    int ld_row = tid >> 2, ld_kc = (tid & 3) * 8;

    int lm_a_base = wm * (MF * 16) + (lane & 15);
    int lm_a_col = (lane >> 4) * 8;
    int lm_b_base = wn * 32 + ((lane >> 4) & 1) * 8 + (lane & 7);
    int lm_b_col = ((lane >> 3) & 1) * 8;

    float acc[MF][4][4];
#pragma unroll
    for (int mf = 0; mf < MF; mf++)
#pragma unroll
        for (int nf = 0; nf < 4; nf++)
#pragma unroll
            for (int j = 0; j < 4; j++) acc[mf][nf][j] = 0.f;

    auto load_stage = [&](int stage, int c) {
        uint32_t s = sb + stage * STAGE;
        int kg = c * GBK + ld_kc;
        bool kp = kg < K;
#pragma unroll
        for (int i = 0; i < 2; i++) {
            int row = ld_row + i * 64;
            size_t off = kp ? ((size_t)(bm + row) * K + kg) : 0;
            uint32_t sa = s + (uint32_t)(row * LDA + ld_kc) * 2;
            cp16(sa + SM_AH, Ah + off, kp);
            cp16(sa + SM_AL, Al + off, kp);
        }
#pragma unroll
        for (int i = 0; i < BN / 64; i++) {
            int row = ld_row + i * 64;
            bool wp = kp && (bn + row) < N;
            size_t off = wp ? ((size_t)(bn + row) * K + kg) : 0;
            uint32_t sa = s + (uint32_t)(row * LDA + ld_kc) * 2;
            cp16(sa + SM_W, Wh + off, wp);
            if (TERMS == 3) cp16(sa + SM_WL, Wl + off, wp);
        }
        cp_commit();
    };

    auto compute_stage = [&](int stage) {
        uint32_t s = sb + stage * STAGE;
#pragma unroll
        for (int kk = 0; kk < GBK; kk += 16) {
            uint32_t ah[MF][4], al[MF][4];
#pragma unroll
            for (int mf = 0; mf < MF; mf++) {
                uint32_t aoff = (uint32_t)((lm_a_base + mf * 16) * LDA + kk + lm_a_col) * 2;
                ldm_x4(s + SM_AH + aoff, ah[mf]);
                ldm_x4(s + SM_AL + aoff, al[mf]);
            }
            uint32_t bw[4][2], bl[4][2];
#pragma unroll
            for (int p = 0; p < 2; p++) {
                uint32_t boff = (uint32_t)((lm_b_base + p * 16) * LDA + kk + lm_b_col) * 2;
                uint32_t r[4];
                ldm_x4(s + SM_W + boff, r);
                bw[2 * p][0] = r[0]; bw[2 * p][1] = r[1];
                bw[2 * p + 1][0] = r[2]; bw[2 * p + 1][1] = r[3];
                if (TERMS == 3) {
                    ldm_x4(s + SM_WL + boff, r);
                    bl[2 * p][0] = r[0]; bl[2 * p][1] = r[1];
                    bl[2 * p + 1][0] = r[2]; bl[2 * p + 1][1] = r[3];
                }
            }
#pragma unroll
            for (int mf = 0; mf < MF; mf++)
#pragma unroll
                for (int nf = 0; nf < 4; nf++) {
                    mma16816(acc[mf][nf], ah[mf], bw[nf]);
                    mma16816(acc[mf][nf], al[mf], bw[nf]);
                    if (TERMS == 3) mma16816(acc[mf][nf], ah[mf], bl[nf]);
                }
        }
    };

    load_stage(0, 0);
    if (nch > 1) load_stage(1, 1); else cp_commit();
    for (int c = 0; c < nch; c++) {
        if (c + 1 <= nch - 1) cp_wait<1>(); else cp_wait<0>();
        __syncthreads();
        int nc = c + STAGES - 1;
        if (nc < nch) load_stage(nc % STAGES, nc);
        compute_stage(c % STAGES);
    }

    if (cvw == nullptr) {
        // ---- plain epilogue ----
        int m0 = bm + wm * (MF * 16) + (lane >> 2);
        int n0 = bn + wn * 32 + 2 * (lane & 3);
#pragma unroll
        for (int mf = 0; mf < MF; mf++) {
            int r0 = m0 + mf * 16;
#pragma unroll
            for (int nf = 0; nf < 4; nf++) {
                int cc = n0 + nf * 8;
                if (cc < N) {
                    const float* a = acc[mf][nf];
                    if (C) {
                        *(float2*)(C + (size_t)r0 * N + cc) = make_float2(a[0], a[1]);
                        *(float2*)(C + (size_t)(r0 + 8) * N + cc) = make_float2(a[2], a[3]);
                    }
                    if (Ch) {
#pragma unroll
                        for (int j = 0; j < 4; j++) {
                            size_t o = (size_t)(r0 + (j >> 1) * 8) * N + cc + (j & 1);
                            float v = a[j];
                            f16 h = __float2half_rn(v);
                            Ch[o] = h;
                            Cl[o] = __float2half_rn(v - __half2float(h));
                        }
                    }
                }
            }
        }
    } else {
        // ---- fused conv+silu+split / z epilogue (in_proj only) ----
        __syncthreads();                    // pipeline smem now reusable
        float* st = (float*)smem;           // [3 halo + 128 rows][EPL]
        // 1. stage acc tile (rows offset by 3)
#pragma unroll
        for (int mf = 0; mf < MF; mf++)
#pragma unroll
            for (int nf = 0; nf < 4; nf++)
#pragma unroll
                for (int j = 0; j < 4; j++) {
                    int row = wm * (MF * 16) + mf * 16 + (lane >> 2) + (j >> 1) * 8;
                    int col = wn * 32 + nf * 8 + 2 * (lane & 3) + (j & 1);
                    st[(row + 3) * EPL + col] = acc[mf][nf][j];
                }
        // 2. halo rows (GEMM rows bm-3..bm-1) via SIMT dot; zero at batch start
        int l0 = bm & (L_SZ - 1);
        for (int idx = tid; idx < 3 * 128; idx += 256) {
            int r = idx >> 7, col = idx & 127;
            int gcol = bn + col;
            float v = 0.f;
            if (l0 != 0 && gcol < DI) {     // halo only needed for conv (x) columns
                const f16* ar = Ah + (size_t)(bm - 3 + r) * K;
                const f16* al = Al + (size_t)(bm - 3 + r) * K;
                const f16* wr = Wh + (size_t)gcol * K;
                for (int k = 0; k < K; k++)
                    v = fmaf(__half2float(ar[k]) + __half2float(al[k]),
                             __half2float(wr[k]), v);
            }
            st[r * EPL + col] = v;
        }
        __syncthreads();
        // 3. per-column conv / z write
        int col = tid & 127;
        int gcol = bn + col;
        if (gcol < TWO_DI) {
            bool isx = gcol < DI;
            float w0 = 0.f, w1 = 0.f, w2 = 0.f, w3 = 0.f, bias = 0.f;
            if (isx) {
                w0 = __ldg(&cvw[gcol * 4 + 0]); w1 = __ldg(&cvw[gcol * 4 + 1]);
                w2 = __ldg(&cvw[gcol * 4 + 2]); w3 = __ldg(&cvw[gcol * 4 + 3]);
                bias = __ldg(&cvb[gcol]);
            }
            for (int r = (tid >> 7); r < 128; r += 2) {
                size_t m = (size_t)(bm + r);
                if (isx) {
                    float a = bias;
                    a = fmaf(st[(r + 0) * EPL + col], w0, a);
                    a = fmaf(st[(r + 1) * EPL + col], w1, a);
                    a = fmaf(st[(r + 2) * EPL + col], w2, a);
                    a = fmaf(st[(r + 3) * EPL + col], w3, a);
                    float sig = 1.f / (1.f + __expf(-a));
                    float rv = a * sig;
                    f16 h = __float2half_rn(rv);
                    cXh[m * DI + gcol] = h;
                    cXl[m * DI + gcol] = __float2half_rn(rv - __half2float(h));
                } else {
                    cZ[m * DI + (gcol - DI)] = st[(r + 3) * EPL + col];
                }
            }
        }
    }
}

#define GSM_128 (STAGES * (20480 + 128 * 80))       // 92160 (TERMS=2)
#define GSM_64T3 (STAGES * (20480 + 2 * 64 * 80))   // 92160 (TERMS=3)

// ---------------- vectorized split fp32 -> (hi, lo) fp16 ----------------
__global__ void split_kernel(const float4* __restrict__ src, __half2* __restrict__ hi,
                             __half2* __restrict__ lo, int n4)
{
    int i = blockIdx.x * blockDim.x + threadIdx.x;
    if (i >= n4) return;
    float4 v = src[i];
    f16 h0 = __float2half_rn(v.x), h1 = __float2half_rn(v.y);
    f16 h2 = __float2half_rn(v.z), h3 = __float2half_rn(v.w);
    hi[2 * i] = __halves2half2(h0, h1);
    hi[2 * i + 1] = __halves2half2(h2, h3);
    lo[2 * i] = __halves2half2(__float2half_rn(v.x - __half2float(h0)),
                               __float2half_rn(v.y - __half2float(h1)));
    lo[2 * i + 1] = __halves2half2(__float2half_rn(v.z - __half2float(h2)),
                                   __float2half_rn(v.w - __half2float(h3)));
}

// ---------------- vectorized convert fp32 -> fp16 ----------------
__global__ void cvt_kernel(const float4* __restrict__ src, __half2* __restrict__ dst, int n4)
{
    int i = blockIdx.x * blockDim.x + threadIdx.x;
    if (i >= n4) return;
    float4 v = src[i];
    dst[2 * i] = __halves2half2(__float2half_rn(v.x), __float2half_rn(v.y));
    dst[2 * i + 1] = __halves2half2(__float2half_rn(v.z), __float2half_rn(v.w));
}

// ---- detect S4D-real structure: Ac[n] == -(n+1) ----
__device__ __forceinline__ bool a_is_s4d(const float* Ac) {
    bool ok = true;
#pragma unroll
    for (int n = 0; n < DS; n++) ok = ok && (fabsf(Ac[n] + (float)(n + 1)) < 1e-3f);
    return ok;
}

__device__ __forceinline__ float softplus_f(float x) {
    return (x > 20.f) ? x : __logf(1.f + __expf(x));
}

// ---------------- scan pass 1: inline dt, chunk-local h_end + sum dt ----------------
__global__ void scan_pass1(const f16* __restrict__ xch, const f16* __restrict__ xcl,
                           const float* __restrict__ proj,
                           const float* __restrict__ dtw, const float* __restrict__ dtb,
                           const float* __restrict__ Alog,
                           float* __restrict__ hend, float* __restrict__ sdt_out)
{
    int ch = blockIdx.x;
    int b = blockIdx.y;
    int c = threadIdx.x;              // blockDim = 560
    __shared__ float Bs[CHL][DS];
    __shared__ float ps[CHL][DTR];

    int m0 = b * L_SZ + ch * CHL;
    for (int idx = c; idx < CHL * DS; idx += blockDim.x) {
        int i = idx >> 4, n = idx & 15;
        Bs[i][n] = proj[(size_t)(m0 + i) * NPROJ + DTR + n];
    }
    for (int idx = c; idx < CHL * DTR; idx += blockDim.x) {
        int i = idx / DTR, r = idx % DTR;
        ps[i][r] = proj[(size_t)(m0 + i) * NPROJ + r];
    }
    __syncthreads();

    float w[DTR];
#pragma unroll
    for (int r = 0; r < DTR; r++) w[r] = __ldg(&dtw[c * DTR + r]);
    float bias = __ldg(&dtb[c]);

    float Ac[DS];
#pragma unroll
    for (int n = 0; n < DS; n++) Ac[n] = -__expf(__ldg(&Alog[c * DS + n]));
    bool fast = a_is_s4d(Ac);

    float h[DS];
#pragma unroll
    for (int n = 0; n < DS; n++) h[n] = 0.f;
    float sdt = 0.f;

    for (int i = 0; i < CHL; i++) {
        size_t m = (size_t)(m0 + i);
        float dacc = bias;
#pragma unroll
        for (int r = 0; r < DTR; r++) dacc = fmaf(ps[i][r], w[r], dacc);
        float dtv = softplus_f(dacc);
        float uv = __half2float(xch[m * DI + c]) + __half2float(xcl[m * DI + c]);
        sdt += dtv;
        float s = dtv * uv;
        if (fast) {
            float e1 = __expf(-dtv);
            float p = e1;
#pragma unroll
            for (int n = 0; n < DS; n++) {
                h[n] = fmaf(p, h[n], s * Bs[i][n]);
                p *= e1;
            }
        } else {
#pragma unroll
            for (int n = 0; n < DS; n++) {
                float dA = __expf(dtv * Ac[n]);
                h[n] = fmaf(dA, h[n], s * Bs[i][n]);
            }
        }
    }

    size_t base = ((size_t)ch * B_SZ + b) * DI + c;
    sdt_out[base] = sdt;
#pragma unroll
    for (int n = 0; n < DS; n++) hend[base * DS + n] = h[n];
}

// ---------------- scan pass 2: inter-chunk prefix ----------------
__global__ void scan_pass2(const float* __restrict__ Alog,
                           const float* __restrict__ sdt,
                           const float* __restrict__ hend,
                           float* __restrict__ hinit)
{
    int t = blockIdx.x * blockDim.x + threadIdx.x;
    if (t >= B_SZ * DI * DS) return;
    int n = t & 15;
    int c = (t >> 4) % DI;
    int b = t / (DS * DI);

    float A = -__expf(__ldg(&Alog[c * DS + n]));
    float hp = 0.f;
    for (int k = 0; k < NCH; k++) {
        size_t base = ((size_t)k * B_SZ + b) * DI + c;
        hinit[base * DS + n] = hp;
        hp = fmaf(__expf(A * sdt[base]), hp, hend[base * DS + n]);
    }
}

// ---------------- scan pass 3: inline dt, rescan, y + u*D, gate, split ----------------
__global__ void scan_pass3(const f16* __restrict__ xch, const f16* __restrict__ xcl,
                           const float* __restrict__ proj,
                           const float* __restrict__ dtw, const float* __restrict__ dtb,
                           const float* __restrict__ zbuf,
                           const float* __restrict__ Alog,
                           const float* __restrict__ Dv,
                           const float* __restrict__ hinit,
                           f16* __restrict__ yh, f16* __restrict__ yl)
{
    int ch = blockIdx.x;
    int b = blockIdx.y;
    int c = threadIdx.x;              // blockDim = 560
    __shared__ float Bs[CHL][DS];
    __shared__ float Cs[CHL][DS];
    __shared__ float ps[CHL][DTR];

    int m0 = b * L_SZ + ch * CHL;
    for (int idx = c; idx < CHL * DS; idx += blockDim.x) {
        int i = idx >> 4, n = idx & 15;
        const float* p = proj + (size_t)(m0 + i) * NPROJ + DTR;
        Bs[i][n] = p[n];
        Cs[i][n] = p[DS + n];
    }
    for (int idx = c; idx < CHL * DTR; idx += blockDim.x) {
        int i = idx / DTR, r = idx % DTR;
        ps[i][r] = proj[(size_t)(m0 + i) * NPROJ + r];
    }
    __syncthreads();

    float w[DTR];
#pragma unroll
    for (int r = 0; r < DTR; r++) w[r] = __ldg(&dtw[c * DTR + r]);
    float bias = __ldg(&dtb[c]);

    float Ac[DS];
#pragma unroll
    for (int n = 0; n < DS; n++) Ac[n] = -__expf(__ldg(&Alog[c * DS + n]));
    bool fast = a_is_s4d(Ac);
    float Dc = __ldg(&Dv[c]);

    size_t base = ((size_t)ch * B_SZ + b) * DI + c;
    float h[DS];
#pragma unroll
    for (int n = 0; n < DS; n++) h[n] = hinit[base * DS + n];

    for (int i = 0; i < CHL; i++) {
        size_t m = (size_t)(m0 + i);
        float dacc = bias;
#pragma unroll
        for (int r = 0; r < DTR; r++) dacc = fmaf(ps[i][r], w[r], dacc);
        float dtv = softplus_f(dacc);
        float uv = __half2float(xch[m * DI + c]) + __half2float(xcl[m * DI + c]);
        float s = dtv * uv;
        float y = uv * Dc;
        if (fast) {
            float e1 = __expf(-dtv);
            float p = e1;
#pragma unroll
            for (int n = 0; n < DS; n++) {
                h[n] = fmaf(p, h[n], s * Bs[i][n]);
                y = fmaf(h[n], Cs[i][n], y);
                p *= e1;
            }
        } else {
#pragma unroll
            for (int n = 0; n < DS; n++) {
                float dA = __expf(dtv * Ac[n]);
                h[n] = fmaf(dA, h[n], s * Bs[i][n]);
                y = fmaf(h[n], Cs[i][n], y);
            }
        }
        float z = zbuf[m * DI + c];
        float sig = 1.f / (1.f + __expf(-z));
        float yv = y * (z * sig);
        f16 hh = __float2half_rn(yv);
        yh[m * DI + c] = hh;
        yl[m * DI + c] = __float2half_rn(yv - __half2float(hh));
    }
}

// ---------------- host launch ----------------
extern "C" void kernel_launch(void* const* d_in, const int* in_sizes, int n_in,
                              void* d_out, int out_size)
{
    (void)in_sizes; (void)n_in; (void)out_size;
    const float* x_in = (const float*)d_in[0];
    const float* inw  = (const float*)d_in[1];
    const float* cw   = (const float*)d_in[2];
    const float* cb   = (const float*)d_in[3];
    const float* xpw  = (const float*)d_in[4];
    const float* dtw  = (const float*)d_in[5];
    const float* dtb  = (const float*)d_in[6];
    const float* alog = (const float*)d_in[7];
    const float* Dv   = (const float*)d_in[8];
    const float* ow   = (const float*)d_in[9];
    float* out = (float*)d_out;

    float *p_z, *p_proj, *p_hend, *p_hinit, *p_sdt;
    f16 *p_xh, *p_xl, *p_xch, *p_xcl, *p_yh, *p_yl;
    f16 *p_wih, *p_wxh, *p_wxl, *p_woh;
    cudaGetSymbolAddress((void**)&p_z, g_z);
    cudaGetSymbolAddress((void**)&p_proj, g_proj);
    cudaGetSymbolAddress((void**)&p_hend, g_hend);
    cudaGetSymbolAddress((void**)&p_hinit, g_hinit);
    cudaGetSymbolAddress((void**)&p_sdt, g_sdt);
    cudaGetSymbolAddress((void**)&p_xh, g_xh);
    cudaGetSymbolAddress((void**)&p_xl, g_xl);
    cudaGetSymbolAddress((void**)&p_xch, g_xch);
    cudaGetSymbolAddress((void**)&p_xcl, g_xcl);
    cudaGetSymbolAddress((void**)&p_yh, g_yh);
    cudaGetSymbolAddress((void**)&p_yl, g_yl);
    cudaGetSymbolAddress((void**)&p_wih, g_wih);
    cudaGetSymbolAddress((void**)&p_wxh, g_wxh);
    cudaGetSymbolAddress((void**)&p_wxl, g_wxl);
    cudaGetSymbolAddress((void**)&p_woh, g_woh);

    cudaFuncSetAttribute((const void*)&gemm_f16s<128, 2>, cudaFuncAttributeMaxDynamicSharedMemorySize, GSM_128);
    cudaFuncSetAttribute((const void*)&gemm_f16s<64, 3>, cudaFuncAttributeMaxDynamicSharedMemorySize, GSM_64T3);

    // weights: in/out single fp16; x_proj split pair; input x split pair
    {
        int n1 = 3 * TWO_DI * DM / 4;
        cvt_kernel<<<(n1 + 255) / 256, 256>>>((const float4*)inw, (__half2*)p_wih, n1);
        int n2 = 3 * NPROJ * DI / 4;
        split_kernel<<<(n2 + 255) / 256, 256>>>((const float4*)xpw, (__half2*)p_wxh, (__half2*)p_wxl, n2);
        int n3 = 3 * DM * DI / 4;
        cvt_kernel<<<(n3 + 255) / 256, 256>>>((const float4*)ow, (__half2*)p_woh, n3);
        int n4 = ML * DM / 4;
        split_kernel<<<(n4 + 255) / 256, 256>>>((const float4*)x_in, (__half2*)p_xh, (__half2*)p_xl, n4);
    }

    for (int i = 0; i < 3; i++) {
        const f16* l_wih = p_wih + (size_t)i * TWO_DI * DM;
        const f16* l_wxh = p_wxh + (size_t)i * NPROJ * DI;
        const f16* l_wxl = p_wxl + (size_t)i * NPROJ * DI;
        const f16* l_woh = p_woh + (size_t)i * DM * DI;
        const float* l_cw   = cw   + (size_t)i * DI * 4;
        const float* l_cb   = cb   + (size_t)i * DI;
        const float* l_dtw  = dtw  + (size_t)i * DI * DTR;
        const float* l_dtb  = dtb  + (size_t)i * DI;
        const float* l_alog = alog + (size_t)i * DI * DS;
        const float* l_Dv   = Dv   + (size_t)i * DI;

        // 1. in_proj + fused conv/silu/split + z passthrough
        gemm_f16s<128, 2><<<dim3((TWO_DI + 127) / 128, ML / 128), 256, GSM_128>>>(
            p_xh, p_xl, l_wih, nullptr, nullptr, nullptr, nullptr,
            l_cw, l_cb, p_xch, p_xcl, p_z, TWO_DI, DM);

        // 2. x_proj: proj = xc @ xpw^T  (32768 x 50, K=560), 3-term
        gemm_f16s<64, 3><<<dim3(1, ML / 128), 256, GSM_64T3>>>(
            p_xch, p_xcl, l_wxh, l_wxl, p_proj, nullptr, nullptr,
            nullptr, nullptr, nullptr, nullptr, nullptr, NPROJ, DI);

        // 3. selective scan (3-pass chunked, dt inline)
        {
            dim3 grid(NCH, B_SZ);
            scan_pass1<<<grid, DI>>>(p_xch, p_xcl, p_proj, l_dtw, l_dtb, l_alog, p_hend, p_sdt);
            int t2 = B_SZ * DI * DS;
            scan_pass2<<<(t2 + 255) / 256, 256>>>(l_alog, p_sdt, p_hend, p_hinit);
            scan_pass3<<<grid, DI>>>(p_xch, p_xcl, p_proj, l_dtw, l_dtb, p_z,
                                     l_alog, l_Dv, p_hinit, p_yh, p_yl);
        }

        // 4. out_proj: x_next = y @ ow^T  (32768 x 280, K=560)
        if (i < 2) {
            gemm_f16s<128, 2><<<dim3((DM + 127) / 128, ML / 128), 256, GSM_128>>>(
                p_yh, p_yl, l_woh, nullptr, nullptr, p_xh, p_xl,
                nullptr, nullptr, nullptr, nullptr, nullptr, DM, DI);
        } else {
            gemm_f16s<128, 2><<<dim3((DM + 127) / 128, ML / 128), 256, GSM_128>>>(
                p_yh, p_yl, l_woh, nullptr, out, nullptr, nullptr,
                nullptr, nullptr, nullptr, nullptr, nullptr, DM, DI);
        }
    }
}

// round 12
// speedup vs baseline: 1.3057x; 1.3057x over previous
#include <cuda_runtime.h>
#include <cuda_fp16.h>
#include <cstdint>

// ---------------- problem constants ----------------
#define B_SZ 8
#define L_SZ 4096
#define ML (B_SZ * L_SZ)        // 32768
#define DM 280
#define DI 560
#define DS 16
#define DTR 18
#define NPROJ (DTR + 2 * DS)    // 50
#define TWO_DI (2 * DI)         // 1120
#define NCH 64
#define CHL (L_SZ / NCH)        // 64

typedef __half f16;

// ---------------- scratch (static device memory; no allocs) ----------------
__device__ float g_xz[(size_t)ML * TWO_DI];
__device__ float g_proj[(size_t)ML * NPROJ];
__device__ float g_hend[(size_t)NCH * B_SZ * DI * DS];
__device__ float g_hinit[(size_t)NCH * B_SZ * DI * DS];
__device__ float g_sdt[(size_t)NCH * B_SZ * DI];

__device__ __align__(256) f16 g_xh[(size_t)ML * DM];
__device__ __align__(256) f16 g_xl[(size_t)ML * DM];
__device__ __align__(256) f16 g_xch[(size_t)ML * DI];
__device__ __align__(256) f16 g_xcl[(size_t)ML * DI];
__device__ __align__(256) f16 g_yh[(size_t)ML * DI];
__device__ __align__(256) f16 g_yl[(size_t)ML * DI];
__device__ __align__(256) f16 g_wih[(size_t)3 * TWO_DI * DM];
__device__ __align__(256) f16 g_wxh[(size_t)3 * NPROJ * DI];
__device__ __align__(256) f16 g_wxl[(size_t)3 * NPROJ * DI];
__device__ __align__(256) f16 g_woh[(size_t)3 * DM * DI];

// ---------------- PTX helpers (sm_100 base ISA only: HMMA/ldmatrix/cp.async) ----
__device__ __forceinline__ uint32_t smem_u32(const void* p) {
    uint32_t a;
    asm("{ .reg .u64 t; cvta.to.shared.u64 t, %1; cvt.u32.u64 %0, t; }" : "=r"(a) : "l"(p));
    return a;
}
__device__ __forceinline__ void cp16(uint32_t dst, const void* src, bool pred) {
    int sz = pred ? 16 : 0;
    asm volatile("cp.async.cg.shared.global [%0], [%1], 16, %2;"
                 :: "r"(dst), "l"(src), "r"(sz) : "memory");
}
__device__ __forceinline__ void cp_commit() {
    asm volatile("cp.async.commit_group;" ::: "memory");
}
template <int N>
__device__ __forceinline__ void cp_wait() {
    asm volatile("cp.async.wait_group %0;" :: "n"(N) : "memory");
}
__device__ __forceinline__ void ldm_x4(uint32_t addr, uint32_t* r) {
    asm volatile("ldmatrix.sync.aligned.m8n8.x4.shared.b16 {%0,%1,%2,%3}, [%4];"
                 : "=r"(r[0]), "=r"(r[1]), "=r"(r[2]), "=r"(r[3]) : "r"(addr));
}
__device__ __forceinline__ void mma16816(float* c, const uint32_t* a, const uint32_t* b) {
    asm volatile("mma.sync.aligned.m16n8k16.row.col.f32.f16.f16.f32 "
                 "{%0,%1,%2,%3}, {%4,%5,%6,%7}, {%8,%9}, {%0,%1,%2,%3};"
                 : "+f"(c[0]), "+f"(c[1]), "+f"(c[2]), "+f"(c[3])
                 : "r"(a[0]), "r"(a[1]), "r"(a[2]), "r"(a[3]), "r"(b[0]), "r"(b[1]));
}

// ---------------- HMMA fp16 GEMM: C[M,N] = A[M,K] * W[N,K]^T ----------------
// TERMS=2: D = AhWh + AlWh (W single fp16). TERMS=3: + AhWl (W split).
// CTA tile 128 x BN x 32. 8 warps. 3-stage cp.async pipeline, ONE sync per chunk.
#define GBK 32
#define LDA 40                   // f16 elems/row (32 + 8 pad); row stride 80B
#define STAGES 3

template <int BN, int TERMS>
__global__ __launch_bounds__(256) void gemm_f16s(
    const f16* __restrict__ Ah, const f16* __restrict__ Al,
    const f16* __restrict__ Wh, const f16* __restrict__ Wl,
    float* __restrict__ C, f16* __restrict__ Ch, f16* __restrict__ Cl,
    int N, int K)
{
    constexpr int NWN = BN / 32;            // warps along N
    constexpr int MF = (128 / (8 / NWN)) / 16; // m-frags per warp
    constexpr int SM_AH = 0;
    constexpr int SM_AL = 10240;
    constexpr int SM_W  = 20480;
    constexpr int SM_WL = 20480 + BN * 80;
    constexpr int STAGE = 20480 + BN * 80 * (TERMS - 1);

    extern __shared__ char smem[];
    uint32_t sb = smem_u32(smem);
    int tid = threadIdx.x;
    int lane = tid & 31, wid = tid >> 5;
    int wm = wid / NWN, wn = wid % NWN;
    int bm = blockIdx.y * 128, bn = blockIdx.x * BN;
    int nch = (K + GBK - 1) / GBK;

    int ld_row = tid >> 2, ld_kc = (tid & 3) * 8;

    int lm_a_base = wm * (MF * 16) + (lane & 15);
    int lm_a_col = (lane >> 4) * 8;
    int lm_b_base = wn * 32 + ((lane >> 4) & 1) * 8 + (lane & 7);
    int lm_b_col = ((lane >> 3) & 1) * 8;

    float acc[MF][4][4];
#pragma unroll
    for (int mf = 0; mf < MF; mf++)
#pragma unroll
        for (int nf = 0; nf < 4; nf++)
#pragma unroll
            for (int j = 0; j < 4; j++) acc[mf][nf][j] = 0.f;

    auto load_stage = [&](int stage, int c) {
        uint32_t s = sb + stage * STAGE;
        int kg = c * GBK + ld_kc;
        bool kp = kg < K;
#pragma unroll
        for (int i = 0; i < 2; i++) {
            int row = ld_row + i * 64;
            size_t off = kp ? ((size_t)(bm + row) * K + kg) : 0;
            uint32_t sa = s + (uint32_t)(row * LDA + ld_kc) * 2;
            cp16(sa + SM_AH, Ah + off, kp);
            cp16(sa + SM_AL, Al + off, kp);
        }
#pragma unroll
        for (int i = 0; i < BN / 64; i++) {
            int row = ld_row + i * 64;
            bool wp = kp && (bn + row) < N;
            size_t off = wp ? ((size_t)(bn + row) * K + kg) : 0;
            uint32_t sa = s + (uint32_t)(row * LDA + ld_kc) * 2;
            cp16(sa + SM_W, Wh + off, wp);
            if (TERMS == 3) cp16(sa + SM_WL, Wl + off, wp);
        }
        cp_commit();
    };

    auto compute_stage = [&](int stage) {
        uint32_t s = sb + stage * STAGE;
#pragma unroll
        for (int kk = 0; kk < GBK; kk += 16) {
            uint32_t ah[MF][4], al[MF][4];
#pragma unroll
            for (int mf = 0; mf < MF; mf++) {
                uint32_t aoff = (uint32_t)((lm_a_base + mf * 16) * LDA + kk + lm_a_col) * 2;
                ldm_x4(s + SM_AH + aoff, ah[mf]);
                ldm_x4(s + SM_AL + aoff, al[mf]);
            }
            uint32_t bw[4][2], bl[4][2];
#pragma unroll
            for (int p = 0; p < 2; p++) {
                uint32_t boff = (uint32_t)((lm_b_base + p * 16) * LDA + kk + lm_b_col) * 2;
                uint32_t r[4];
                ldm_x4(s + SM_W + boff, r);
                bw[2 * p][0] = r[0]; bw[2 * p][1] = r[1];
                bw[2 * p + 1][0] = r[2]; bw[2 * p + 1][1] = r[3];
                if (TERMS == 3) {
                    ldm_x4(s + SM_WL + boff, r);
                    bl[2 * p][0] = r[0]; bl[2 * p][1] = r[1];
                    bl[2 * p + 1][0] = r[2]; bl[2 * p + 1][1] = r[3];
                }
            }
#pragma unroll
            for (int mf = 0; mf < MF; mf++)
#pragma unroll
                for (int nf = 0; nf < 4; nf++) {
                    mma16816(acc[mf][nf], ah[mf], bw[nf]);
                    mma16816(acc[mf][nf], al[mf], bw[nf]);
                    if (TERMS == 3) mma16816(acc[mf][nf], ah[mf], bl[nf]);
                }
        }
    };

    load_stage(0, 0);
    if (nch > 1) load_stage(1, 1); else cp_commit();
    for (int c = 0; c < nch; c++) {
        if (c + 1 <= nch - 1) cp_wait<1>(); else cp_wait<0>();
        __syncthreads();
        int nc = c + STAGES - 1;
        if (nc < nch) load_stage(nc % STAGES, nc);
        compute_stage(c % STAGES);
    }

    // ---- epilogue ----
    int m0 = bm + wm * (MF * 16) + (lane >> 2);
    int n0 = bn + wn * 32 + 2 * (lane & 3);
#pragma unroll
    for (int mf = 0; mf < MF; mf++) {
        int r0 = m0 + mf * 16;
#pragma unroll
        for (int nf = 0; nf < 4; nf++) {
            int cc = n0 + nf * 8;
            if (cc < N) {
                const float* a = acc[mf][nf];
                if (C) {
                    *(float2*)(C + (size_t)r0 * N + cc) = make_float2(a[0], a[1]);
                    *(float2*)(C + (size_t)(r0 + 8) * N + cc) = make_float2(a[2], a[3]);
                }
                if (Ch) {
#pragma unroll
                    for (int j = 0; j < 4; j++) {
                        size_t o = (size_t)(r0 + (j >> 1) * 8) * N + cc + (j & 1);
                        float v = a[j];
                        f16 h = __float2half_rn(v);
                        Ch[o] = h;
                        Cl[o] = __float2half_rn(v - __half2float(h));
                    }
                }
            }
        }
    }
}

#define GSM_128 (STAGES * (20480 + 128 * 80))       // 92160 (TERMS=2)
#define GSM_64T3 (STAGES * (20480 + 2 * 64 * 80))   // 92160 (TERMS=3)

// ---------------- vectorized split fp32 -> (hi, lo) fp16 ----------------
__global__ void split_kernel(const float4* __restrict__ src, __half2* __restrict__ hi,
                             __half2* __restrict__ lo, int n4)
{
    int i = blockIdx.x * blockDim.x + threadIdx.x;
    if (i >= n4) return;
    float4 v = src[i];
    f16 h0 = __float2half_rn(v.x), h1 = __float2half_rn(v.y);
    f16 h2 = __float2half_rn(v.z), h3 = __float2half_rn(v.w);
    hi[2 * i] = __halves2half2(h0, h1);
    hi[2 * i + 1] = __halves2half2(h2, h3);
    lo[2 * i] = __halves2half2(__float2half_rn(v.x - __half2float(h0)),
                               __float2half_rn(v.y - __half2float(h1)));
    lo[2 * i + 1] = __halves2half2(__float2half_rn(v.z - __half2float(h2)),
                                   __float2half_rn(v.w - __half2float(h3)));
}

// ---------------- vectorized convert fp32 -> fp16 ----------------
__global__ void cvt_kernel(const float4* __restrict__ src, __half2* __restrict__ dst, int n4)
{
    int i = blockIdx.x * blockDim.x + threadIdx.x;
    if (i >= n4) return;
    float4 v = src[i];
    dst[2 * i] = __halves2half2(__float2half_rn(v.x), __float2half_rn(v.y));
    dst[2 * i + 1] = __halves2half2(__float2half_rn(v.z), __float2half_rn(v.w));
}

// ---------------- conv1d (depthwise causal K=4) + silu + split, 8 l per thread ----
#define CONV_T 8
__global__ void conv_silu_kernel(const float* __restrict__ xz,
                                 const float* __restrict__ cw,
                                 const float* __restrict__ cb,
                                 f16* __restrict__ xch, f16* __restrict__ xcl)
{
    int c = threadIdx.x;                  // blockDim = 560
    int l0 = blockIdx.x * CONV_T;
    int b = blockIdx.y;

    float w0 = __ldg(&cw[c * 4 + 0]), w1 = __ldg(&cw[c * 4 + 1]);
    float w2 = __ldg(&cw[c * 4 + 2]), w3 = __ldg(&cw[c * 4 + 3]);
    float bias = __ldg(&cb[c]);

    const float* base = xz + ((size_t)(b * L_SZ + l0)) * TWO_DI + c;
    float v[CONV_T + 3];
#pragma unroll
    for (int j = 0; j < CONV_T + 3; j++) {
        int l = l0 - 3 + j;
        v[j] = (l >= 0) ? base[(j - 3) * TWO_DI] : 0.f;
    }

#pragma unroll
    for (int t = 0; t < CONV_T; t++) {
        float acc = bias;
        acc = fmaf(v[t], w0, acc);
        acc = fmaf(v[t + 1], w1, acc);
        acc = fmaf(v[t + 2], w2, acc);
        acc = fmaf(v[t + 3], w3, acc);
        float sig = 1.f / (1.f + __expf(-acc));
        float r = acc * sig;
        f16 h = __float2half_rn(r);
        size_t o = (size_t)(b * L_SZ + l0 + t) * DI + c;
        xch[o] = h;
        xcl[o] = __float2half_rn(r - __half2float(h));
    }
}

// ---- detect S4D-real structure: Ac[n] == -(n+1) ----
__device__ __forceinline__ bool a_is_s4d(const float* Ac) {
    bool ok = true;
#pragma unroll
    for (int n = 0; n < DS; n++) ok = ok && (fabsf(Ac[n] + (float)(n + 1)) < 1e-3f);
    return ok;
}

__device__ __forceinline__ float softplus_f(float x) {
    return (x > 20.f) ? x : __logf(1.f + __expf(x));
}

// ---------------- scan pass 1: inline dt, chunk-local h_end + sum dt ----------------
__global__ void scan_pass1(const f16* __restrict__ xch, const f16* __restrict__ xcl,
                           const float* __restrict__ proj,
                           const float* __restrict__ dtw, const float* __restrict__ dtb,
                           const float* __restrict__ Alog,
                           float* __restrict__ hend, float* __restrict__ sdt_out)
{
    int ch = blockIdx.x;
    int b = blockIdx.y;
    int c = threadIdx.x;              // blockDim = 560
    __shared__ float Bs[CHL][DS];
    __shared__ float ps[CHL][DTR];

    int m0 = b * L_SZ + ch * CHL;
    for (int idx = c; idx < CHL * DS; idx += blockDim.x) {
        int i = idx >> 4, n = idx & 15;
        Bs[i][n] = proj[(size_t)(m0 + i) * NPROJ + DTR + n];
    }
    for (int idx = c; idx < CHL * DTR; idx += blockDim.x) {
        int i = idx / DTR, r = idx % DTR;
        ps[i][r] = proj[(size_t)(m0 + i) * NPROJ + r];
    }
    __syncthreads();

    float w[DTR];
#pragma unroll
    for (int r = 0; r < DTR; r++) w[r] = __ldg(&dtw[c * DTR + r]);
    float bias = __ldg(&dtb[c]);

    float Ac[DS];
#pragma unroll
    for (int n = 0; n < DS; n++) Ac[n] = -__expf(__ldg(&Alog[c * DS + n]));
    bool fast = a_is_s4d(Ac);

    float h[DS];
#pragma unroll
    for (int n = 0; n < DS; n++) h[n] = 0.f;
    float sdt = 0.f;

    for (int i = 0; i < CHL; i++) {
        size_t m = (size_t)(m0 + i);
        float dacc = bias;
#pragma unroll
        for (int r = 0; r < DTR; r++) dacc = fmaf(ps[i][r], w[r], dacc);
        float dtv = softplus_f(dacc);
        float uv = __half2float(xch[m * DI + c]) + __half2float(xcl[m * DI + c]);
        sdt += dtv;
        float s = dtv * uv;
        if (fast) {
            float e1 = __expf(-dtv);
            float p = e1;
#pragma unroll
            for (int n = 0; n < DS; n++) {
                h[n] = fmaf(p, h[n], s * Bs[i][n]);
                p *= e1;
            }
        } else {
#pragma unroll
            for (int n = 0; n < DS; n++) {
                float dA = __expf(dtv * Ac[n]);
                h[n] = fmaf(dA, h[n], s * Bs[i][n]);
            }
        }
    }

    size_t base = ((size_t)ch * B_SZ + b) * DI + c;
    sdt_out[base] = sdt;
#pragma unroll
    for (int n = 0; n < DS; n++) hend[base * DS + n] = h[n];
}

// ---------------- scan pass 2: inter-chunk prefix ----------------
__global__ void scan_pass2(const float* __restrict__ Alog,
                           const float* __restrict__ sdt,
                           const float* __restrict__ hend,
                           float* __restrict__ hinit)
{
    int t = blockIdx.x * blockDim.x + threadIdx.x;
    if (t >= B_SZ * DI * DS) return;
    int n = t & 15;
    int c = (t >> 4) % DI;
    int b = t / (DS * DI);

    float A = -__expf(__ldg(&Alog[c * DS + n]));
    float hp = 0.f;
    for (int k = 0; k < NCH; k++) {
        size_t base = ((size_t)k * B_SZ + b) * DI + c;
        hinit[base * DS + n] = hp;
        hp = fmaf(__expf(A * sdt[base]), hp, hend[base * DS + n]);
    }
}

// ---------------- scan pass 3: inline dt, rescan, y + u*D, gate, split ----------------
__global__ void scan_pass3(const f16* __restrict__ xch, const f16* __restrict__ xcl,
                           const float* __restrict__ proj,
                           const float* __restrict__ dtw, const float* __restrict__ dtb,
                           const float* __restrict__ xz,
                           const float* __restrict__ Alog,
                           const float* __restrict__ Dv,
                           const float* __restrict__ hinit,
                           f16* __restrict__ yh, f16* __restrict__ yl)
{
    int ch = blockIdx.x;
    int b = blockIdx.y;
    int c = threadIdx.x;              // blockDim = 560
    __shared__ float Bs[CHL][DS];
    __shared__ float Cs[CHL][DS];
    __shared__ float ps[CHL][DTR];

    int m0 = b * L_SZ + ch * CHL;
    for (int idx = c; idx < CHL * DS; idx += blockDim.x) {
        int i = idx >> 4, n = idx & 15;
        const float* p = proj + (size_t)(m0 + i) * NPROJ + DTR;
        Bs[i][n] = p[n];
        Cs[i][n] = p[DS + n];
    }
    for (int idx = c; idx < CHL * DTR; idx += blockDim.x) {
        int i = idx / DTR, r = idx % DTR;
        ps[i][r] = proj[(size_t)(m0 + i) * NPROJ + r];
    }
    __syncthreads();

    float w[DTR];
#pragma unroll
    for (int r = 0; r < DTR; r++) w[r] = __ldg(&dtw[c * DTR + r]);
    float bias = __ldg(&dtb[c]);

    float Ac[DS];
#pragma unroll
    for (int n = 0; n < DS; n++) Ac[n] = -__expf(__ldg(&Alog[c * DS + n]));
    bool fast = a_is_s4d(Ac);
    float Dc = __ldg(&Dv[c]);

    size_t base = ((size_t)ch * B_SZ + b) * DI + c;
    float h[DS];
#pragma unroll
    for (int n = 0; n < DS; n++) h[n] = hinit[base * DS + n];

    for (int i = 0; i < CHL; i++) {
        size_t m = (size_t)(m0 + i);
        float dacc = bias;
#pragma unroll
        for (int r = 0; r < DTR; r++) dacc = fmaf(ps[i][r], w[r], dacc);
        float dtv = softplus_f(dacc);
        float uv = __half2float(xch[m * DI + c]) + __half2float(xcl[m * DI + c]);
        float s = dtv * uv;
        float y = uv * Dc;
        if (fast) {
            float e1 = __expf(-dtv);
            float p = e1;
#pragma unroll
            for (int n = 0; n < DS; n++) {
                h[n] = fmaf(p, h[n], s * Bs[i][n]);
                y = fmaf(h[n], Cs[i][n], y);
                p *= e1;
            }
        } else {
#pragma unroll
            for (int n = 0; n < DS; n++) {
                float dA = __expf(dtv * Ac[n]);
                h[n] = fmaf(dA, h[n], s * Bs[i][n]);
                y = fmaf(h[n], Cs[i][n], y);
            }
        }
        float z = xz[m * TWO_DI + DI + c];
        float sig = 1.f / (1.f + __expf(-z));
        float yv = y * (z * sig);
        f16 hh = __float2half_rn(yv);
        yh[m * DI + c] = hh;
        yl[m * DI + c] = __float2half_rn(yv - __half2float(hh));
    }
}

// ---------------- host launch ----------------
extern "C" void kernel_launch(void* const* d_in, const int* in_sizes, int n_in,
                              void* d_out, int out_size)
{
    (void)in_sizes; (void)n_in; (void)out_size;
    const float* x_in = (const float*)d_in[0];
    const float* inw  = (const float*)d_in[1];
    const float* cw   = (const float*)d_in[2];
    const float* cb   = (const float*)d_in[3];
    const float* xpw  = (const float*)d_in[4];
    const float* dtw  = (const float*)d_in[5];
    const float* dtb  = (const float*)d_in[6];
    const float* alog = (const float*)d_in[7];
    const float* Dv   = (const float*)d_in[8];
    const float* ow   = (const float*)d_in[9];
    float* out = (float*)d_out;

    float *p_xz, *p_proj, *p_hend, *p_hinit, *p_sdt;
    f16 *p_xh, *p_xl, *p_xch, *p_xcl, *p_yh, *p_yl;
    f16 *p_wih, *p_wxh, *p_wxl, *p_woh;
    cudaGetSymbolAddress((void**)&p_xz, g_xz);
    cudaGetSymbolAddress((void**)&p_proj, g_proj);
    cudaGetSymbolAddress((void**)&p_hend, g_hend);
    cudaGetSymbolAddress((void**)&p_hinit, g_hinit);
    cudaGetSymbolAddress((void**)&p_sdt, g_sdt);
    cudaGetSymbolAddress((void**)&p_xh, g_xh);
    cudaGetSymbolAddress((void**)&p_xl, g_xl);
    cudaGetSymbolAddress((void**)&p_xch, g_xch);
    cudaGetSymbolAddress((void**)&p_xcl, g_xcl);
    cudaGetSymbolAddress((void**)&p_yh, g_yh);
    cudaGetSymbolAddress((void**)&p_yl, g_yl);
    cudaGetSymbolAddress((void**)&p_wih, g_wih);
    cudaGetSymbolAddress((void**)&p_wxh, g_wxh);
    cudaGetSymbolAddress((void**)&p_wxl, g_wxl);
    cudaGetSymbolAddress((void**)&p_woh, g_woh);

    cudaFuncSetAttribute((const void*)&gemm_f16s<128, 2>, cudaFuncAttributeMaxDynamicSharedMemorySize, GSM_128);
    cudaFuncSetAttribute((const void*)&gemm_f16s<64, 3>, cudaFuncAttributeMaxDynamicSharedMemorySize, GSM_64T3);

    // weights: in/out single fp16; x_proj split pair; input x split pair (vectorized)
    {
        int n1 = 3 * TWO_DI * DM / 4;
        cvt_kernel<<<(n1 + 255) / 256, 256>>>((const float4*)inw, (__half2*)p_wih, n1);
        int n2 = 3 * NPROJ * DI / 4;
        split_kernel<<<(n2 + 255) / 256, 256>>>((const float4*)xpw, (__half2*)p_wxh, (__half2*)p_wxl, n2);
        int n3 = 3 * DM * DI / 4;
        cvt_kernel<<<(n3 + 255) / 256, 256>>>((const float4*)ow, (__half2*)p_woh, n3);
        int n4 = ML * DM / 4;
        split_kernel<<<(n4 + 255) / 256, 256>>>((const float4*)x_in, (__half2*)p_xh, (__half2*)p_xl, n4);
    }

    for (int i = 0; i < 3; i++) {
        const f16* l_wih = p_wih + (size_t)i * TWO_DI * DM;
        const f16* l_wxh = p_wxh + (size_t)i * NPROJ * DI;
        const f16* l_wxl = p_wxl + (size_t)i * NPROJ * DI;
        const f16* l_woh = p_woh + (size_t)i * DM * DI;
        const float* l_cw   = cw   + (size_t)i * DI * 4;
        const float* l_cb   = cb   + (size_t)i * DI;
        const float* l_dtw  = dtw  + (size_t)i * DI * DTR;
        const float* l_dtb  = dtb  + (size_t)i * DI;
        const float* l_alog = alog + (size_t)i * DI * DS;
        const float* l_Dv   = Dv   + (size_t)i * DI;

        // 1. in_proj: xz = x @ inw^T   (32768 x 1120, K=280)
        gemm_f16s<128, 2><<<dim3((TWO_DI + 127) / 128, ML / 128), 256, GSM_128>>>(
            p_xh, p_xl, l_wih, nullptr, p_xz, nullptr, nullptr, TWO_DI, DM);

        // 2. causal conv + silu -> xc fp16 pair only
        conv_silu_kernel<<<dim3(L_SZ / CONV_T, B_SZ), DI>>>(p_xz, l_cw, l_cb, p_xch, p_xcl);

        // 3. x_proj: proj = xc @ xpw^T  (32768 x 50, K=560), 3-term
        gemm_f16s<64, 3><<<dim3(1, ML / 128), 256, GSM_64T3>>>(
            p_xch, p_xcl, l_wxh, l_wxl, p_proj, nullptr, nullptr, NPROJ, DI);

        // 4. selective scan (3-pass chunked, dt inline)
        {
            dim3 grid(NCH, B_SZ);
            scan_pass1<<<grid, DI>>>(p_xch, p_xcl, p_proj, l_dtw, l_dtb, l_alog, p_hend, p_sdt);
            int t2 = B_SZ * DI * DS;
            scan_pass2<<<(t2 + 255) / 256, 256>>>(l_alog, p_sdt, p_hend, p_hinit);
            scan_pass3<<<grid, DI>>>(p_xch, p_xcl, p_proj, l_dtw, l_dtb, p_xz,
                                     l_alog, l_Dv, p_hinit, p_yh, p_yl);
        }

        // 5. out_proj: x_next = y @ ow^T  (32768 x 280, K=560)
        if (i < 2) {
            gemm_f16s<128, 2><<<dim3((DM + 127) / 128, ML / 128), 256, GSM_128>>>(
                p_yh, p_yl, l_woh, nullptr, nullptr, p_xh, p_xl, DM, DI);
        } else {
            gemm_f16s<128, 2><<<dim3((DM + 127) / 128, ML / 128), 256, GSM_128>>>(
                p_yh, p_yl, l_woh, nullptr, out, nullptr, nullptr, DM, DI);
        }
    }
}

// round 14
// speedup vs baseline: 1.3909x; 1.0653x over previous
#include <cuda_runtime.h>
#include <cuda_fp16.h>
#include <cstdint>

// ---------------- problem constants ----------------
#define B_SZ 8
#define L_SZ 4096
#define ML (B_SZ * L_SZ)        // 32768
#define DM 280
#define DI 560
#define DS 16
#define DTR 18
#define NPROJ (DTR + 2 * DS)    // 50
#define TWO_DI (2 * DI)         // 1120
#define NCH 32
#define CHL (L_SZ / NCH)        // 128

typedef __half f16;

// ---------------- scratch (static device memory; no allocs) ----------------
__device__ float g_xz[(size_t)ML * TWO_DI];
__device__ float g_proj[(size_t)ML * NPROJ];
__device__ float g_hend[(size_t)NCH * B_SZ * DI * DS];
__device__ float g_hinit[(size_t)NCH * B_SZ * DI * DS];
__device__ float g_sdt[(size_t)NCH * B_SZ * DI];

__device__ __align__(256) f16 g_xh[(size_t)ML * DM];
__device__ __align__(256) f16 g_xl[(size_t)ML * DM];
__device__ __align__(256) f16 g_xch[(size_t)ML * DI];
__device__ __align__(256) f16 g_xcl[(size_t)ML * DI];
__device__ __align__(256) f16 g_yh[(size_t)ML * DI];
__device__ __align__(256) f16 g_yl[(size_t)ML * DI];
__device__ __align__(256) f16 g_wih[(size_t)3 * TWO_DI * DM];
__device__ __align__(256) f16 g_wxh[(size_t)3 * NPROJ * DI];
__device__ __align__(256) f16 g_wxl[(size_t)3 * NPROJ * DI];
__device__ __align__(256) f16 g_woh[(size_t)3 * DM * DI];

// ---------------- PTX helpers (sm_100 base ISA only: HMMA/ldmatrix/cp.async) ----
__device__ __forceinline__ uint32_t smem_u32(const void* p) {
    uint32_t a;
    asm("{ .reg .u64 t; cvta.to.shared.u64 t, %1; cvt.u32.u64 %0, t; }" : "=r"(a) : "l"(p));
    return a;
}
__device__ __forceinline__ void cp16(uint32_t dst, const void* src, bool pred) {
    int sz = pred ? 16 : 0;
    asm volatile("cp.async.cg.shared.global [%0], [%1], 16, %2;"
                 :: "r"(dst), "l"(src), "r"(sz) : "memory");
}
__device__ __forceinline__ void cp_commit() {
    asm volatile("cp.async.commit_group;" ::: "memory");
}
template <int N>
__device__ __forceinline__ void cp_wait() {
    asm volatile("cp.async.wait_group %0;" :: "n"(N) : "memory");
}
__device__ __forceinline__ void ldm_x4(uint32_t addr, uint32_t* r) {
    asm volatile("ldmatrix.sync.aligned.m8n8.x4.shared.b16 {%0,%1,%2,%3}, [%4];"
                 : "=r"(r[0]), "=r"(r[1]), "=r"(r[2]), "=r"(r[3]) : "r"(addr));
}
__device__ __forceinline__ void mma16816(float* c, const uint32_t* a, const uint32_t* b) {
    asm volatile("mma.sync.aligned.m16n8k16.row.col.f32.f16.f16.f32 "
                 "{%0,%1,%2,%3}, {%4,%5,%6,%7}, {%8,%9}, {%0,%1,%2,%3};"
                 : "+f"(c[0]), "+f"(c[1]), "+f"(c[2]), "+f"(c[3])
                 : "r"(a[0]), "r"(a[1]), "r"(a[2]), "r"(a[3]), "r"(b[0]), "r"(b[1]));
}

// ---------------- HMMA fp16 GEMM: C[M,N] = A[M,K] * W[N,K]^T ----------------
// TERMS=2: D = AhWh + AlWh (W single fp16). TERMS=3: + AhWl (W split).
// CTA tile 128 x BN x 32. 8 warps. 3-stage cp.async pipeline, ONE sync per chunk.
#define GBK 32
#define LDA 40                   // f16 elems/row (32 + 8 pad); row stride 80B
#define STAGES 3

template <int BN, int TERMS>
__global__ __launch_bounds__(256) void gemm_f16s(
    const f16* __restrict__ Ah, const f16* __restrict__ Al,
    const f16* __restrict__ Wh, const f16* __restrict__ Wl,
    float* __restrict__ C, f16* __restrict__ Ch, f16* __restrict__ Cl,
    int N, int K)
{
    constexpr int NWN = BN / 32;            // warps along N
    constexpr int MF = (128 / (8 / NWN)) / 16; // m-frags per warp
    constexpr int SM_AH = 0;
    constexpr int SM_AL = 10240;
    constexpr int SM_W  = 20480;
    constexpr int SM_WL = 20480 + BN * 80;
    constexpr int STAGE = 20480 + BN * 80 * (TERMS - 1);

    extern __shared__ char smem[];
    uint32_t sb = smem_u32(smem);
    int tid = threadIdx.x;
    int lane = tid & 31, wid = tid >> 5;
    int wm = wid / NWN, wn = wid % NWN;
    int bm = blockIdx.y * 128, bn = blockIdx.x * BN;
    int nch = (K + GBK - 1) / GBK;

    int ld_row = tid >> 2, ld_kc = (tid & 3) * 8;

    int lm_a_base = wm * (MF * 16) + (lane & 15);
    int lm_a_col = (lane >> 4) * 8;
    int lm_b_base = wn * 32 + ((lane >> 4) & 1) * 8 + (lane & 7);
    int lm_b_col = ((lane >> 3) & 1) * 8;

    float acc[MF][4][4];
#pragma unroll
    for (int mf = 0; mf < MF; mf++)
#pragma unroll
        for (int nf = 0; nf < 4; nf++)
#pragma unroll
            for (int j = 0; j < 4; j++) acc[mf][nf][j] = 0.f;

    auto load_stage = [&](int stage, int c) {
        uint32_t s = sb + stage * STAGE;
        int kg = c * GBK + ld_kc;
        bool kp = kg < K;
#pragma unroll
        for (int i = 0; i < 2; i++) {
            int row = ld_row + i * 64;
            size_t off = kp ? ((size_t)(bm + row) * K + kg) : 0;
            uint32_t sa = s + (uint32_t)(row * LDA + ld_kc) * 2;
            cp16(sa + SM_AH, Ah + off, kp);
            cp16(sa + SM_AL, Al + off, kp);
        }
#pragma unroll
        for (int i = 0; i < BN / 64; i++) {
            int row = ld_row + i * 64;
            bool wp = kp && (bn + row) < N;
            size_t off = wp ? ((size_t)(bn + row) * K + kg) : 0;
            uint32_t sa = s + (uint32_t)(row * LDA + ld_kc) * 2;
            cp16(sa + SM_W, Wh + off, wp);
            if (TERMS == 3) cp16(sa + SM_WL, Wl + off, wp);
        }
        cp_commit();
    };

    auto compute_stage = [&](int stage) {
        uint32_t s = sb + stage * STAGE;
#pragma unroll
        for (int kk = 0; kk < GBK; kk += 16) {
            uint32_t ah[MF][4], al[MF][4];
#pragma unroll
            for (int mf = 0; mf < MF; mf++) {
                uint32_t aoff = (uint32_t)((lm_a_base + mf * 16) * LDA + kk + lm_a_col) * 2;
                ldm_x4(s + SM_AH + aoff, ah[mf]);
                ldm_x4(s + SM_AL + aoff, al[mf]);
            }
            uint32_t bw[4][2], bl[4][2];
#pragma unroll
            for (int p = 0; p < 2; p++) {
                uint32_t boff = (uint32_t)((lm_b_base + p * 16) * LDA + kk + lm_b_col) * 2;
                uint32_t r[4];
                ldm_x4(s + SM_W + boff, r);
                bw[2 * p][0] = r[0]; bw[2 * p][1] = r[1];
                bw[2 * p + 1][0] = r[2]; bw[2 * p + 1][1] = r[3];
                if (TERMS == 3) {
                    ldm_x4(s + SM_WL + boff, r);
                    bl[2 * p][0] = r[0]; bl[2 * p][1] = r[1];
                    bl[2 * p + 1][0] = r[2]; bl[2 * p + 1][1] = r[3];
                }
            }
#pragma unroll
            for (int mf = 0; mf < MF; mf++)
#pragma unroll
                for (int nf = 0; nf < 4; nf++) {
                    mma16816(acc[mf][nf], ah[mf], bw[nf]);
                    mma16816(acc[mf][nf], al[mf], bw[nf]);
                    if (TERMS == 3) mma16816(acc[mf][nf], ah[mf], bl[nf]);
                }
        }
    };

    load_stage(0, 0);
    if (nch > 1) load_stage(1, 1); else cp_commit();
    for (int c = 0; c < nch; c++) {
        if (c + 1 <= nch - 1) cp_wait<1>(); else cp_wait<0>();
        __syncthreads();
        int nc = c + STAGES - 1;
        if (nc < nch) load_stage(nc % STAGES, nc);
        compute_stage(c % STAGES);
    }

    // ---- epilogue ----
    int m0 = bm + wm * (MF * 16) + (lane >> 2);
    int n0 = bn + wn * 32 + 2 * (lane & 3);
#pragma unroll
    for (int mf = 0; mf < MF; mf++) {
        int r0 = m0 + mf * 16;
#pragma unroll
        for (int nf = 0; nf < 4; nf++) {
            int cc = n0 + nf * 8;
            if (cc < N) {
                const float* a = acc[mf][nf];
                if (C) {
                    *(float2*)(C + (size_t)r0 * N + cc) = make_float2(a[0], a[1]);
                    *(float2*)(C + (size_t)(r0 + 8) * N + cc) = make_float2(a[2], a[3]);
                }
                if (Ch) {
#pragma unroll
                    for (int rr = 0; rr < 2; rr++) {   // rows r0, r0+8; cc even -> half2 aligned
                        size_t o = (size_t)(r0 + rr * 8) * N + cc;
                        float v0 = a[rr * 2], v1 = a[rr * 2 + 1];
                        f16 h0 = __float2half_rn(v0), h1 = __float2half_rn(v1);
                        *(__half2*)(Ch + o) = __halves2half2(h0, h1);
                        *(__half2*)(Cl + o) = __halves2half2(
                            __float2half_rn(v0 - __half2float(h0)),
                            __float2half_rn(v1 - __half2float(h1)));
                    }
                }
            }
        }
    }
}

#define GSM_128 (STAGES * (20480 + 128 * 80))       // 92160 (TERMS=2)
#define GSM_64T3 (STAGES * (20480 + 2 * 64 * 80))   // 92160 (TERMS=3)

// ---------------- vectorized split fp32 -> (hi, lo) fp16 ----------------
__global__ void split_kernel(const float4* __restrict__ src, __half2* __restrict__ hi,
                             __half2* __restrict__ lo, int n4)
{
    int i = blockIdx.x * blockDim.x + threadIdx.x;
    if (i >= n4) return;
    float4 v = src[i];
    f16 h0 = __float2half_rn(v.x), h1 = __float2half_rn(v.y);
    f16 h2 = __float2half_rn(v.z), h3 = __float2half_rn(v.w);
    hi[2 * i] = __halves2half2(h0, h1);
    hi[2 * i + 1] = __halves2half2(h2, h3);
    lo[2 * i] = __halves2half2(__float2half_rn(v.x - __half2float(h0)),
                               __float2half_rn(v.y - __half2float(h1)));
    lo[2 * i + 1] = __halves2half2(__float2half_rn(v.z - __half2float(h2)),
                                   __float2half_rn(v.w - __half2float(h3)));
}

// ---------------- vectorized convert fp32 -> fp16 ----------------
__global__ void cvt_kernel(const float4* __restrict__ src, __half2* __restrict__ dst, int n4)
{
    int i = blockIdx.x * blockDim.x + threadIdx.x;
    if (i >= n4) return;
    float4 v = src[i];
    dst[2 * i] = __halves2half2(__float2half_rn(v.x), __float2half_rn(v.y));
    dst[2 * i + 1] = __halves2half2(__float2half_rn(v.z), __float2half_rn(v.w));
}

// ---------------- conv1d (depthwise causal K=4) + silu + split, 16 l per thread ----
#define CONV_T 16
__global__ void conv_silu_kernel(const float* __restrict__ xz,
                                 const float* __restrict__ cw,
                                 const float* __restrict__ cb,
                                 f16* __restrict__ xch, f16* __restrict__ xcl)
{
    int c = threadIdx.x;                  // blockDim = 560
    int l0 = blockIdx.x * CONV_T;
    int b = blockIdx.y;

    float w0 = __ldg(&cw[c * 4 + 0]), w1 = __ldg(&cw[c * 4 + 1]);
    float w2 = __ldg(&cw[c * 4 + 2]), w3 = __ldg(&cw[c * 4 + 3]);
    float bias = __ldg(&cb[c]);

    const float* base = xz + ((size_t)(b * L_SZ + l0)) * TWO_DI + c;
    float v[CONV_T + 3];
#pragma unroll
    for (int j = 0; j < CONV_T + 3; j++) {
        int l = l0 - 3 + j;
        v[j] = (l >= 0) ? base[(j - 3) * TWO_DI] : 0.f;
    }

#pragma unroll
    for (int t = 0; t < CONV_T; t++) {
        float acc = bias;
        acc = fmaf(v[t], w0, acc);
        acc = fmaf(v[t + 1], w1, acc);
        acc = fmaf(v[t + 2], w2, acc);
        acc = fmaf(v[t + 3], w3, acc);
        float sig = 1.f / (1.f + __expf(-acc));
        float r = acc * sig;
        f16 h = __float2half_rn(r);
        size_t o = (size_t)(b * L_SZ + l0 + t) * DI + c;
        xch[o] = h;
        xcl[o] = __float2half_rn(r - __half2float(h));
    }
}

// ---- detect S4D-real structure: Ac[n] == -(n+1) ----
__device__ __forceinline__ bool a_is_s4d(const float* Ac) {
    bool ok = true;
#pragma unroll
    for (int n = 0; n < DS; n++) ok = ok && (fabsf(Ac[n] + (float)(n + 1)) < 1e-3f);
    return ok;
}

__device__ __forceinline__ float softplus_f(float x) {
    return (x > 20.f) ? x : __logf(1.f + __expf(x));
}

// ---------------- scan pass 1: inline dt, chunk-local h_end + sum dt ----------------
__global__ void scan_pass1(const f16* __restrict__ xch, const f16* __restrict__ xcl,
                           const float* __restrict__ proj,
                           const float* __restrict__ dtw, const float* __restrict__ dtb,
                           const float* __restrict__ Alog,
                           float* __restrict__ hend, float* __restrict__ sdt_out)
{
    int ch = blockIdx.x;
    int b = blockIdx.y;
    int c = threadIdx.x;              // blockDim = 560
    __shared__ float Bs[CHL][DS];
    __shared__ float ps[CHL][DTR];

    int m0 = b * L_SZ + ch * CHL;
    for (int idx = c; idx < CHL * DS; idx += blockDim.x) {
        int i = idx >> 4, n = idx & 15;
        Bs[i][n] = proj[(size_t)(m0 + i) * NPROJ + DTR + n];
    }
    for (int idx = c; idx < CHL * DTR; idx += blockDim.x) {
        int i = idx / DTR, r = idx % DTR;
        ps[i][r] = proj[(size_t)(m0 + i) * NPROJ + r];
    }
    __syncthreads();

    float w[DTR];
#pragma unroll
    for (int r = 0; r < DTR; r++) w[r] = __ldg(&dtw[c * DTR + r]);
    float bias = __ldg(&dtb[c]);

    float Ac[DS];
#pragma unroll
    for (int n = 0; n < DS; n++) Ac[n] = -__expf(__ldg(&Alog[c * DS + n]));
    bool fast = a_is_s4d(Ac);

    float h[DS];
#pragma unroll
    for (int n = 0; n < DS; n++) h[n] = 0.f;
    float sdt = 0.f;

    for (int i = 0; i < CHL; i++) {
        size_t m = (size_t)(m0 + i);
        float dacc = bias;
#pragma unroll
        for (int r = 0; r < DTR; r++) dacc = fmaf(ps[i][r], w[r], dacc);
        float dtv = softplus_f(dacc);
        float uv = __half2float(xch[m * DI + c]) + __half2float(xcl[m * DI + c]);
        sdt += dtv;
        float s = dtv * uv;
        if (fast) {
            float e1 = __expf(-dtv);
            float p = e1;
#pragma unroll
            for (int n = 0; n < DS; n++) {
                h[n] = fmaf(p, h[n], s * Bs[i][n]);
                p *= e1;
            }
        } else {
#pragma unroll
            for (int n = 0; n < DS; n++) {
                float dA = __expf(dtv * Ac[n]);
                h[n] = fmaf(dA, h[n], s * Bs[i][n]);
            }
        }
    }

    size_t base = ((size_t)ch * B_SZ + b) * DI + c;
    sdt_out[base] = sdt;
#pragma unroll
    for (int n = 0; n < DS; n++) hend[base * DS + n] = h[n];
}

// ---------------- scan pass 2: inter-chunk prefix ----------------
__global__ void scan_pass2(const float* __restrict__ Alog,
                           const float* __restrict__ sdt,
                           const float* __restrict__ hend,
                           float* __restrict__ hinit)
{
    int t = blockIdx.x * blockDim.x + threadIdx.x;
    if (t >= B_SZ * DI * DS) return;
    int n = t & 15;
    int c = (t >> 4) % DI;
    int b = t / (DS * DI);

    float A = -__expf(__ldg(&Alog[c * DS + n]));
    float hp = 0.f;
    for (int k = 0; k < NCH; k++) {
        size_t base = ((size_t)k * B_SZ + b) * DI + c;
        hinit[base * DS + n] = hp;
        hp = fmaf(__expf(A * sdt[base]), hp, hend[base * DS + n]);
    }
}

// ---------------- scan pass 3: inline dt, rescan, y + u*D, gate, split ----------------
__global__ void scan_pass3(const f16* __restrict__ xch, const f16* __restrict__ xcl,
                           const float* __restrict__ proj,
                           const float* __restrict__ dtw, const float* __restrict__ dtb,
                           const float* __restrict__ xz,
                           const float* __restrict__ Alog,
                           const float* __restrict__ Dv,
                           const float* __restrict__ hinit,
                           f16* __restrict__ yh, f16* __restrict__ yl)
{
    int ch = blockIdx.x;
    int b = blockIdx.y;
    int c = threadIdx.x;              // blockDim = 560
    __shared__ float Bs[CHL][DS];
    __shared__ float Cs[CHL][DS];
    __shared__ float ps[CHL][DTR];

    int m0 = b * L_SZ + ch * CHL;
    for (int idx = c; idx < CHL * DS; idx += blockDim.x) {
        int i = idx >> 4, n = idx & 15;
        const float* p = proj + (size_t)(m0 + i) * NPROJ + DTR;
        Bs[i][n] = p[n];
        Cs[i][n] = p[DS + n];
    }
    for (int idx = c; idx < CHL * DTR; idx += blockDim.x) {
        int i = idx / DTR, r = idx % DTR;
        ps[i][r] = proj[(size_t)(m0 + i) * NPROJ + r];
    }
    __syncthreads();

    float w[DTR];
#pragma unroll
    for (int r = 0; r < DTR; r++) w[r] = __ldg(&dtw[c * DTR + r]);
    float bias = __ldg(&dtb[c]);

    float Ac[DS];
#pragma unroll
    for (int n = 0; n < DS; n++) Ac[n] = -__expf(__ldg(&Alog[c * DS + n]));
    bool fast = a_is_s4d(Ac);
    float Dc = __ldg(&Dv[c]);

    size_t base = ((size_t)ch * B_SZ + b) * DI + c;
    float h[DS];
#pragma unroll
    for (int n = 0; n < DS; n++) h[n] = hinit[base * DS + n];

    for (int i = 0; i < CHL; i++) {
        size_t m = (size_t)(m0 + i);
        float dacc = bias;
#pragma unroll
        for (int r = 0; r < DTR; r++) dacc = fmaf(ps[i][r], w[r], dacc);
        float dtv = softplus_f(dacc);
        float uv = __half2float(xch[m * DI + c]) + __half2float(xcl[m * DI + c]);
        float s = dtv * uv;
        float y = uv * Dc;
        if (fast) {
            float e1 = __expf(-dtv);
            float p = e1;
#pragma unroll
            for (int n = 0; n < DS; n++) {
                h[n] = fmaf(p, h[n], s * Bs[i][n]);
                y = fmaf(h[n], Cs[i][n], y);
                p *= e1;
            }
        } else {
#pragma unroll
            for (int n = 0; n < DS; n++) {
                float dA = __expf(dtv * Ac[n]);
                h[n] = fmaf(dA, h[n], s * Bs[i][n]);
                y = fmaf(h[n], Cs[i][n], y);
            }
        }
        float z = xz[m * TWO_DI + DI + c];
        float sig = 1.f / (1.f + __expf(-z));
        float yv = y * (z * sig);
        f16 hh = __float2half_rn(yv);
        yh[m * DI + c] = hh;
        yl[m * DI + c] = __float2half_rn(yv - __half2float(hh));
    }
}

// ---------------- host launch ----------------
extern "C" void kernel_launch(void* const* d_in, const int* in_sizes, int n_in,
                              void* d_out, int out_size)
{
    (void)in_sizes; (void)n_in; (void)out_size;
    const float* x_in = (const float*)d_in[0];
    const float* inw  = (const float*)d_in[1];
    const float* cw   = (const float*)d_in[2];
    const float* cb   = (const float*)d_in[3];
    const float* xpw  = (const float*)d_in[4];
    const float* dtw  = (const float*)d_in[5];
    const float* dtb  = (const float*)d_in[6];
    const float* alog = (const float*)d_in[7];
    const float* Dv   = (const float*)d_in[8];
    const float* ow   = (const float*)d_in[9];
    float* out = (float*)d_out;

    float *p_xz, *p_proj, *p_hend, *p_hinit, *p_sdt;
    f16 *p_xh, *p_xl, *p_xch, *p_xcl, *p_yh, *p_yl;
    f16 *p_wih, *p_wxh, *p_wxl, *p_woh;
    cudaGetSymbolAddress((void**)&p_xz, g_xz);
    cudaGetSymbolAddress((void**)&p_proj, g_proj);
    cudaGetSymbolAddress((void**)&p_hend, g_hend);
    cudaGetSymbolAddress((void**)&p_hinit, g_hinit);
    cudaGetSymbolAddress((void**)&p_sdt, g_sdt);
    cudaGetSymbolAddress((void**)&p_xh, g_xh);
    cudaGetSymbolAddress((void**)&p_xl, g_xl);
    cudaGetSymbolAddress((void**)&p_xch, g_xch);
    cudaGetSymbolAddress((void**)&p_xcl, g_xcl);
    cudaGetSymbolAddress((void**)&p_yh, g_yh);
    cudaGetSymbolAddress((void**)&p_yl, g_yl);
    cudaGetSymbolAddress((void**)&p_wih, g_wih);
    cudaGetSymbolAddress((void**)&p_wxh, g_wxh);
    cudaGetSymbolAddress((void**)&p_wxl, g_wxl);
    cudaGetSymbolAddress((void**)&p_woh, g_woh);

    cudaFuncSetAttribute((const void*)&gemm_f16s<128, 2>, cudaFuncAttributeMaxDynamicSharedMemorySize, GSM_128);
    cudaFuncSetAttribute((const void*)&gemm_f16s<64, 3>, cudaFuncAttributeMaxDynamicSharedMemorySize, GSM_64T3);

    // weights: in/out single fp16; x_proj split pair; input x split pair (vectorized)
    {
        int n1 = 3 * TWO_DI * DM / 4;
        cvt_kernel<<<(n1 + 255) / 256, 256>>>((const float4*)inw, (__half2*)p_wih, n1);
        int n2 = 3 * NPROJ * DI / 4;
        split_kernel<<<(n2 + 255) / 256, 256>>>((const float4*)xpw, (__half2*)p_wxh, (__half2*)p_wxl, n2);
        int n3 = 3 * DM * DI / 4;
        cvt_kernel<<<(n3 + 255) / 256, 256>>>((const float4*)ow, (__half2*)p_woh, n3);
        int n4 = ML * DM / 4;
        split_kernel<<<(n4 + 255) / 256, 256>>>((const float4*)x_in, (__half2*)p_xh, (__half2*)p_xl, n4);
    }

    for (int i = 0; i < 3; i++) {
        const f16* l_wih = p_wih + (size_t)i * TWO_DI * DM;
        const f16* l_wxh = p_wxh + (size_t)i * NPROJ * DI;
        const f16* l_wxl = p_wxl + (size_t)i * NPROJ * DI;
        const f16* l_woh = p_woh + (size_t)i * DM * DI;
        const float* l_cw   = cw   + (size_t)i * DI * 4;
        const float* l_cb   = cb   + (size_t)i * DI;
        const float* l_dtw  = dtw  + (size_t)i * DI * DTR;
        const float* l_dtb  = dtb  + (size_t)i * DI;
        const float* l_alog = alog + (size_t)i * DI * DS;
        const float* l_Dv   = Dv   + (size_t)i * DI;

        // 1. in_proj: xz = x @ inw^T   (32768 x 1120, K=280)
        gemm_f16s<128, 2><<<dim3((TWO_DI + 127) / 128, ML / 128), 256, GSM_128>>>(
            p_xh, p_xl, l_wih, nullptr, p_xz, nullptr, nullptr, TWO_DI, DM);

        // 2. causal conv + silu -> xc fp16 pair only
        conv_silu_kernel<<<dim3(L_SZ / CONV_T, B_SZ), DI>>>(p_xz, l_cw, l_cb, p_xch, p_xcl);

        // 3. x_proj: proj = xc @ xpw^T  (32768 x 50, K=560), 3-term
        gemm_f16s<64, 3><<<dim3(1, ML / 128), 256, GSM_64T3>>>(
            p_xch, p_xcl, l_wxh, l_wxl, p_proj, nullptr, nullptr, NPROJ, DI);

        // 4. selective scan (3-pass chunked, dt inline)
        {
            dim3 grid(NCH, B_SZ);
            scan_pass1<<<grid, DI>>>(p_xch, p_xcl, p_proj, l_dtw, l_dtb, l_alog, p_hend, p_sdt);
            int t2 = B_SZ * DI * DS;
            scan_pass2<<<(t2 + 255) / 256, 256>>>(l_alog, p_sdt, p_hend, p_hinit);
            scan_pass3<<<grid, DI>>>(p_xch, p_xcl, p_proj, l_dtw, l_dtb, p_xz,
                                     l_alog, l_Dv, p_hinit, p_yh, p_yl);
        }

        // 5. out_proj: x_next = y @ ow^T  (32768 x 280, K=560)
        if (i < 2) {
            gemm_f16s<128, 2><<<dim3((DM + 127) / 128, ML / 128), 256, GSM_128>>>(
                p_yh, p_yl, l_woh, nullptr, nullptr, p_xh, p_xl, DM, DI);
        } else {
            gemm_f16s<128, 2><<<dim3((DM + 127) / 128, ML / 128), 256, GSM_128>>>(
                p_yh, p_yl, l_woh, nullptr, out, nullptr, nullptr, DM, DI);
        }
    }
}

// round 16
// speedup vs baseline: 1.4074x; 1.0118x over previous
#include <cuda_runtime.h>
#include <cuda_fp16.h>
#include <cstdint>

// ---------------- problem constants ----------------
#define B_SZ 8
#define L_SZ 4096
#define ML (B_SZ * L_SZ)        // 32768
#define DM 280
#define DI 560
#define DS 16
#define DTR 18
#define NPROJ (DTR + 2 * DS)    // 50
#define TWO_DI (2 * DI)         // 1120
#define NCH 16
#define CHL (L_SZ / NCH)        // 256
#define SCAN_TPB 280            // scan threads per block (DI/2)

typedef __half f16;

// ---------------- scratch (static device memory; no allocs) ----------------
__device__ float g_xz[(size_t)ML * TWO_DI];
__device__ float g_proj[(size_t)ML * NPROJ];
__device__ float g_hend[(size_t)NCH * B_SZ * DI * DS];
__device__ float g_hinit[(size_t)NCH * B_SZ * DI * DS];
__device__ float g_sdt[(size_t)NCH * B_SZ * DI];

__device__ __align__(256) f16 g_xh[(size_t)ML * DM];
__device__ __align__(256) f16 g_xl[(size_t)ML * DM];
__device__ __align__(256) f16 g_xch[(size_t)ML * DI];
__device__ __align__(256) f16 g_xcl[(size_t)ML * DI];
__device__ __align__(256) f16 g_yh[(size_t)ML * DI];
__device__ __align__(256) f16 g_yl[(size_t)ML * DI];
__device__ __align__(256) f16 g_wih[(size_t)3 * TWO_DI * DM];
__device__ __align__(256) f16 g_wxh[(size_t)3 * NPROJ * DI];
__device__ __align__(256) f16 g_wxl[(size_t)3 * NPROJ * DI];
__device__ __align__(256) f16 g_woh[(size_t)3 * DM * DI];

// ---------------- PTX helpers (sm_100 base ISA only: HMMA/ldmatrix/cp.async) ----
__device__ __forceinline__ uint32_t smem_u32(const void* p) {
    uint32_t a;
    asm("{ .reg .u64 t; cvta.to.shared.u64 t, %1; cvt.u32.u64 %0, t; }" : "=r"(a) : "l"(p));
    return a;
}
__device__ __forceinline__ void cp16(uint32_t dst, const void* src, bool pred) {
    int sz = pred ? 16 : 0;
    asm volatile("cp.async.cg.shared.global [%0], [%1], 16, %2;"
                 :: "r"(dst), "l"(src), "r"(sz) : "memory");
}
__device__ __forceinline__ void cp_commit() {
    asm volatile("cp.async.commit_group;" ::: "memory");
}
template <int N>
__device__ __forceinline__ void cp_wait() {
    asm volatile("cp.async.wait_group %0;" :: "n"(N) : "memory");
}
__device__ __forceinline__ void ldm_x4(uint32_t addr, uint32_t* r) {
    asm volatile("ldmatrix.sync.aligned.m8n8.x4.shared.b16 {%0,%1,%2,%3}, [%4];"
                 : "=r"(r[0]), "=r"(r[1]), "=r"(r[2]), "=r"(r[3]) : "r"(addr));
}
__device__ __forceinline__ void mma16816(float* c, const uint32_t* a, const uint32_t* b) {
    asm volatile("mma.sync.aligned.m16n8k16.row.col.f32.f16.f16.f32 "
                 "{%0,%1,%2,%3}, {%4,%5,%6,%7}, {%8,%9}, {%0,%1,%2,%3};"
                 : "+f"(c[0]), "+f"(c[1]), "+f"(c[2]), "+f"(c[3])
                 : "r"(a[0]), "r"(a[1]), "r"(a[2]), "r"(a[3]), "r"(b[0]), "r"(b[1]));
}

// ---------------- HMMA fp16 GEMM: C[M,N] = A[M,K] * W[N,K]^T ----------------
// TERMS=2: D = AhWh + AlWh (W single fp16). TERMS=3: + AhWl (W split).
// CTA tile 128 x BN x 32. 8 warps. 3-stage cp.async pipeline, ONE sync per chunk.
#define GBK 32
#define LDA 40                   // f16 elems/row (32 + 8 pad); row stride 80B
#define STAGES 3

template <int BN, int TERMS>
__global__ __launch_bounds__(256) void gemm_f16s(
    const f16* __restrict__ Ah, const f16* __restrict__ Al,
    const f16* __restrict__ Wh, const f16* __restrict__ Wl,
    float* __restrict__ C, f16* __restrict__ Ch, f16* __restrict__ Cl,
    int N, int K)
{
    constexpr int NWN = BN / 32;            // warps along N
    constexpr int MF = (128 / (8 / NWN)) / 16; // m-frags per warp
    constexpr int SM_AH = 0;
    constexpr int SM_AL = 10240;
    constexpr int SM_W  = 20480;
    constexpr int SM_WL = 20480 + BN * 80;
    constexpr int STAGE = 20480 + BN * 80 * (TERMS - 1);

    extern __shared__ char smem[];
    uint32_t sb = smem_u32(smem);
    int tid = threadIdx.x;
    int lane = tid & 31, wid = tid >> 5;
    int wm = wid / NWN, wn = wid % NWN;
    int bm = blockIdx.y * 128, bn = blockIdx.x * BN;
    int nch = (K + GBK - 1) / GBK;

    int ld_row = tid >> 2, ld_kc = (tid & 3) * 8;

    int lm_a_base = wm * (MF * 16) + (lane & 15);
    int lm_a_col = (lane >> 4) * 8;
    int lm_b_base = wn * 32 + ((lane >> 4) & 1) * 8 + (lane & 7);
    int lm_b_col = ((lane >> 3) & 1) * 8;

    float acc[MF][4][4];
#pragma unroll
    for (int mf = 0; mf < MF; mf++)
#pragma unroll
        for (int nf = 0; nf < 4; nf++)
#pragma unroll
            for (int j = 0; j < 4; j++) acc[mf][nf][j] = 0.f;

    auto load_stage = [&](int stage, int c) {
        uint32_t s = sb + stage * STAGE;
        int kg = c * GBK + ld_kc;
        bool kp = kg < K;
#pragma unroll
        for (int i = 0; i < 2; i++) {
            int row = ld_row + i * 64;
            size_t off = kp ? ((size_t)(bm + row) * K + kg) : 0;
            uint32_t sa = s + (uint32_t)(row * LDA + ld_kc) * 2;
            cp16(sa + SM_AH, Ah + off, kp);
            cp16(sa + SM_AL, Al + off, kp);
        }
#pragma unroll
        for (int i = 0; i < BN / 64; i++) {
            int row = ld_row + i * 64;
            bool wp = kp && (bn + row) < N;
            size_t off = wp ? ((size_t)(bn + row) * K + kg) : 0;
            uint32_t sa = s + (uint32_t)(row * LDA + ld_kc) * 2;
            cp16(sa + SM_W, Wh + off, wp);
            if (TERMS == 3) cp16(sa + SM_WL, Wl + off, wp);
        }
        cp_commit();
    };

    auto compute_stage = [&](int stage) {
        uint32_t s = sb + stage * STAGE;
#pragma unroll
        for (int kk = 0; kk < GBK; kk += 16) {
            uint32_t ah[MF][4], al[MF][4];
#pragma unroll
            for (int mf = 0; mf < MF; mf++) {
                uint32_t aoff = (uint32_t)((lm_a_base + mf * 16) * LDA + kk + lm_a_col) * 2;
                ldm_x4(s + SM_AH + aoff, ah[mf]);
                ldm_x4(s + SM_AL + aoff, al[mf]);
            }
            uint32_t bw[4][2], bl[4][2];
#pragma unroll
            for (int p = 0; p < 2; p++) {
                uint32_t boff = (uint32_t)((lm_b_base + p * 16) * LDA + kk + lm_b_col) * 2;
                uint32_t r[4];
                ldm_x4(s + SM_W + boff, r);
                bw[2 * p][0] = r[0]; bw[2 * p][1] = r[1];
                bw[2 * p + 1][0] = r[2]; bw[2 * p + 1][1] = r[3];
                if (TERMS == 3) {
                    ldm_x4(s + SM_WL + boff, r);
                    bl[2 * p][0] = r[0]; bl[2 * p][1] = r[1];
                    bl[2 * p + 1][0] = r[2]; bl[2 * p + 1][1] = r[3];
                }
            }
#pragma unroll
            for (int mf = 0; mf < MF; mf++)
#pragma unroll
                for (int nf = 0; nf < 4; nf++) {
                    mma16816(acc[mf][nf], ah[mf], bw[nf]);
                    mma16816(acc[mf][nf], al[mf], bw[nf]);
                    if (TERMS == 3) mma16816(acc[mf][nf], ah[mf], bl[nf]);
                }
        }
    };

    load_stage(0, 0);
    if (nch > 1) load_stage(1, 1); else cp_commit();
    for (int c = 0; c < nch; c++) {
        if (c + 1 <= nch - 1) cp_wait<1>(); else cp_wait<0>();
        __syncthreads();
        int nc = c + STAGES - 1;
        if (nc < nch) load_stage(nc % STAGES, nc);
        compute_stage(c % STAGES);
    }

    // ---- epilogue ----
    int m0 = bm + wm * (MF * 16) + (lane >> 2);
    int n0 = bn + wn * 32 + 2 * (lane & 3);
#pragma unroll
    for (int mf = 0; mf < MF; mf++) {
        int r0 = m0 + mf * 16;
#pragma unroll
        for (int nf = 0; nf < 4; nf++) {
            int cc = n0 + nf * 8;
            if (cc < N) {
                const float* a = acc[mf][nf];
                if (C) {
                    *(float2*)(C + (size_t)r0 * N + cc) = make_float2(a[0], a[1]);
                    *(float2*)(C + (size_t)(r0 + 8) * N + cc) = make_float2(a[2], a[3]);
                }
                if (Ch) {
#pragma unroll
                    for (int rr = 0; rr < 2; rr++) {   // rows r0, r0+8; cc even -> half2 aligned
                        size_t o = (size_t)(r0 + rr * 8) * N + cc;
                        float v0 = a[rr * 2], v1 = a[rr * 2 + 1];
                        f16 h0 = __float2half_rn(v0), h1 = __float2half_rn(v1);
                        *(__half2*)(Ch + o) = __halves2half2(h0, h1);
                        *(__half2*)(Cl + o) = __halves2half2(
                            __float2half_rn(v0 - __half2float(h0)),
                            __float2half_rn(v1 - __half2float(h1)));
                    }
                }
            }
        }
    }
}

#define GSM_128 (STAGES * (20480 + 128 * 80))       // 92160 (TERMS=2)
#define GSM_64T3 (STAGES * (20480 + 2 * 64 * 80))   // 92160 (TERMS=3)

// ---------------- vectorized split fp32 -> (hi, lo) fp16 ----------------
__global__ void split_kernel(const float4* __restrict__ src, __half2* __restrict__ hi,
                             __half2* __restrict__ lo, int n4)
{
    int i = blockIdx.x * blockDim.x + threadIdx.x;
    if (i >= n4) return;
    float4 v = src[i];
    f16 h0 = __float2half_rn(v.x), h1 = __float2half_rn(v.y);
    f16 h2 = __float2half_rn(v.z), h3 = __float2half_rn(v.w);
    hi[2 * i] = __halves2half2(h0, h1);
    hi[2 * i + 1] = __halves2half2(h2, h3);
    lo[2 * i] = __halves2half2(__float2half_rn(v.x - __half2float(h0)),
                               __float2half_rn(v.y - __half2float(h1)));
    lo[2 * i + 1] = __halves2half2(__float2half_rn(v.z - __half2float(h2)),
                                   __float2half_rn(v.w - __half2float(h3)));
}

// ---------------- vectorized convert fp32 -> fp16 ----------------
__global__ void cvt_kernel(const float4* __restrict__ src, __half2* __restrict__ dst, int n4)
{
    int i = blockIdx.x * blockDim.x + threadIdx.x;
    if (i >= n4) return;
    float4 v = src[i];
    dst[2 * i] = __halves2half2(__float2half_rn(v.x), __float2half_rn(v.y));
    dst[2 * i + 1] = __halves2half2(__float2half_rn(v.z), __float2half_rn(v.w));
}

// ---------------- conv1d (depthwise causal K=4) + silu + split, 16 l per thread ----
#define CONV_T 16
__global__ void conv_silu_kernel(const float* __restrict__ xz,
                                 const float* __restrict__ cw,
                                 const float* __restrict__ cb,
                                 f16* __restrict__ xch, f16* __restrict__ xcl)
{
    int c = threadIdx.x;                  // blockDim = 560
    int l0 = blockIdx.x * CONV_T;
    int b = blockIdx.y;

    float w0 = __ldg(&cw[c * 4 + 0]), w1 = __ldg(&cw[c * 4 + 1]);
    float w2 = __ldg(&cw[c * 4 + 2]), w3 = __ldg(&cw[c * 4 + 3]);
    float bias = __ldg(&cb[c]);

    const float* base = xz + ((size_t)(b * L_SZ + l0)) * TWO_DI + c;
    float v[CONV_T + 3];
#pragma unroll
    for (int j = 0; j < CONV_T + 3; j++) {
        int l = l0 - 3 + j;
        v[j] = (l >= 0) ? base[(j - 3) * TWO_DI] : 0.f;
    }

#pragma unroll
    for (int t = 0; t < CONV_T; t++) {
        float acc = bias;
        acc = fmaf(v[t], w0, acc);
        acc = fmaf(v[t + 1], w1, acc);
        acc = fmaf(v[t + 2], w2, acc);
        acc = fmaf(v[t + 3], w3, acc);
        float sig = 1.f / (1.f + __expf(-acc));
        float r = acc * sig;
        f16 h = __float2half_rn(r);
        size_t o = (size_t)(b * L_SZ + l0 + t) * DI + c;
        xch[o] = h;
        xcl[o] = __float2half_rn(r - __half2float(h));
    }
}

// ---- detect S4D-real structure: Ac[n] == -(n+1) ----
__device__ __forceinline__ bool a_is_s4d(const float* Ac) {
    bool ok = true;
#pragma unroll
    for (int n = 0; n < DS; n++) ok = ok && (fabsf(Ac[n] + (float)(n + 1)) < 1e-3f);
    return ok;
}

__device__ __forceinline__ float softplus_f(float x) {
    return (x > 20.f) ? x : __logf(1.f + __expf(x));
}

// ---------------- scan pass 1: inline dt, chunk-local h_end + sum dt ----------------
// grid (NCH, B, 2), blockDim = 280; dynamic smem: Bs[CHL*DS] + ps[CHL*DTR]
__global__ void scan_pass1(const f16* __restrict__ xch, const f16* __restrict__ xcl,
                           const float* __restrict__ proj,
                           const float* __restrict__ dtw, const float* __restrict__ dtb,
                           const float* __restrict__ Alog,
                           float* __restrict__ hend, float* __restrict__ sdt_out)
{
    int ch = blockIdx.x;
    int b = blockIdx.y;
    int c = blockIdx.z * SCAN_TPB + threadIdx.x;
    extern __shared__ float dsm1[];
    float* Bs = dsm1;                    // [CHL][DS]
    float* ps = dsm1 + CHL * DS;         // [CHL][DTR]

    int m0 = b * L_SZ + ch * CHL;
    for (int idx = threadIdx.x; idx < CHL * DS; idx += SCAN_TPB) {
        int i = idx >> 4, n = idx & 15;
        Bs[idx] = proj[(size_t)(m0 + i) * NPROJ + DTR + n];
    }
    for (int idx = threadIdx.x; idx < CHL * DTR; idx += SCAN_TPB) {
        int i = idx / DTR, r = idx % DTR;
        ps[i * DTR + r] = proj[(size_t)(m0 + i) * NPROJ + r];
    }
    __syncthreads();

    float w[DTR];
#pragma unroll
    for (int r = 0; r < DTR; r++) w[r] = __ldg(&dtw[c * DTR + r]);
    float bias = __ldg(&dtb[c]);

    float Ac[DS];
#pragma unroll
    for (int n = 0; n < DS; n++) Ac[n] = -__expf(__ldg(&Alog[c * DS + n]));
    bool fast = a_is_s4d(Ac);

    float h[DS];
#pragma unroll
    for (int n = 0; n < DS; n++) h[n] = 0.f;
    float sdt = 0.f;

    for (int i = 0; i < CHL; i++) {
        size_t m = (size_t)(m0 + i);
        float dacc = bias;
#pragma unroll
        for (int r = 0; r < DTR; r++) dacc = fmaf(ps[i * DTR + r], w[r], dacc);
        float dtv = softplus_f(dacc);
        float uv = __half2float(xch[m * DI + c]) + __half2float(xcl[m * DI + c]);
        sdt += dtv;
        float s = dtv * uv;
        if (fast) {
            float e1 = __expf(-dtv);
            float p = e1;
#pragma unroll
            for (int n = 0; n < DS; n++) {
                h[n] = fmaf(p, h[n], s * Bs[i * DS + n]);
                p *= e1;
            }
        } else {
#pragma unroll
            for (int n = 0; n < DS; n++) {
                float dA = __expf(dtv * Ac[n]);
                h[n] = fmaf(dA, h[n], s * Bs[i * DS + n]);
            }
        }
    }

    size_t base = ((size_t)ch * B_SZ + b) * DI + c;
    sdt_out[base] = sdt;
#pragma unroll
    for (int n = 0; n < DS; n++) hend[base * DS + n] = h[n];
}

// ---------------- scan pass 2: inter-chunk prefix ----------------
__global__ void scan_pass2(const float* __restrict__ Alog,
                           const float* __restrict__ sdt,
                           const float* __restrict__ hend,
                           float* __restrict__ hinit)
{
    int t = blockIdx.x * blockDim.x + threadIdx.x;
    if (t >= B_SZ * DI * DS) return;
    int n = t & 15;
    int c = (t >> 4) % DI;
    int b = t / (DS * DI);

    float A = -__expf(__ldg(&Alog[c * DS + n]));
    float hp = 0.f;
    for (int k = 0; k < NCH; k++) {
        size_t base = ((size_t)k * B_SZ + b) * DI + c;
        hinit[base * DS + n] = hp;
        hp = fmaf(__expf(A * sdt[base]), hp, hend[base * DS + n]);
    }
}

// ---------------- scan pass 3: inline dt, rescan, y + u*D, gate, split ----------------
// grid (NCH, B, 2), blockDim = 280; dynamic smem: Bs + Cs + ps
__global__ void scan_pass3(const f16* __restrict__ xch, const f16* __restrict__ xcl,
                           const float* __restrict__ proj,
                           const float* __restrict__ dtw, const float* __restrict__ dtb,
                           const float* __restrict__ xz,
                           const float* __restrict__ Alog,
                           const float* __restrict__ Dv,
                           const float* __restrict__ hinit,
                           f16* __restrict__ yh, f16* __restrict__ yl)
{
    int ch = blockIdx.x;
    int b = blockIdx.y;
    int c = blockIdx.z * SCAN_TPB + threadIdx.x;
    extern __shared__ float dsm3[];
    float* Bs = dsm3;                       // [CHL][DS]
    float* Cs = dsm3 + CHL * DS;            // [CHL][DS]
    float* ps = dsm3 + 2 * CHL * DS;        // [CHL][DTR]

    int m0 = b * L_SZ + ch * CHL;
    for (int idx = threadIdx.x; idx < CHL * DS; idx += SCAN_TPB) {
        int i = idx >> 4, n = idx & 15;
        const float* p = proj + (size_t)(m0 + i) * NPROJ + DTR;
        Bs[idx] = p[n];
        Cs[idx] = p[DS + n];
    }
    for (int idx = threadIdx.x; idx < CHL * DTR; idx += SCAN_TPB) {
        int i = idx / DTR, r = idx % DTR;
        ps[i * DTR + r] = proj[(size_t)(m0 + i) * NPROJ + r];
    }
    __syncthreads();

    float w[DTR];
#pragma unroll
    for (int r = 0; r < DTR; r++) w[r] = __ldg(&dtw[c * DTR + r]);
    float bias = __ldg(&dtb[c]);

    float Ac[DS];
#pragma unroll
    for (int n = 0; n < DS; n++) Ac[n] = -__expf(__ldg(&Alog[c * DS + n]));
    bool fast = a_is_s4d(Ac);
    float Dc = __ldg(&Dv[c]);

    size_t base = ((size_t)ch * B_SZ + b) * DI + c;
    float h[DS];
#pragma unroll
    for (int n = 0; n < DS; n++) h[n] = hinit[base * DS + n];

    for (int i = 0; i < CHL; i++) {
        size_t m = (size_t)(m0 + i);
        float dacc = bias;
#pragma unroll
        for (int r = 0; r < DTR; r++) dacc = fmaf(ps[i * DTR + r], w[r], dacc);
        float dtv = softplus_f(dacc);
        float uv = __half2float(xch[m * DI + c]) + __half2float(xcl[m * DI + c]);
        float s = dtv * uv;
        float y = uv * Dc;
        if (fast) {
            float e1 = __expf(-dtv);
            float p = e1;
#pragma unroll
            for (int n = 0; n < DS; n++) {
                h[n] = fmaf(p, h[n], s * Bs[i * DS + n]);
                y = fmaf(h[n], Cs[i * DS + n], y);
                p *= e1;
            }
        } else {
#pragma unroll
            for (int n = 0; n < DS; n++) {
                float dA = __expf(dtv * Ac[n]);
                h[n] = fmaf(dA, h[n], s * Bs[i * DS + n]);
                y = fmaf(h[n], Cs[i * DS + n], y);
            }
        }
        float z = xz[m * TWO_DI + DI + c];
        float sig = 1.f / (1.f + __expf(-z));
        float yv = y * (z * sig);
        f16 hh = __float2half_rn(yv);
        yh[m * DI + c] = hh;
        yl[m * DI + c] = __float2half_rn(yv - __half2float(hh));
    }
}

#define SMEM_P1 (CHL * (DS + DTR) * 4)          // 34816
#define SMEM_P3 (CHL * (2 * DS + DTR) * 4)      // 51200

// ---------------- host launch ----------------
extern "C" void kernel_launch(void* const* d_in, const int* in_sizes, int n_in,
                              void* d_out, int out_size)
{
    (void)in_sizes; (void)n_in; (void)out_size;
    const float* x_in = (const float*)d_in[0];
    const float* inw  = (const float*)d_in[1];
    const float* cw   = (const float*)d_in[2];
    const float* cb   = (const float*)d_in[3];
    const float* xpw  = (const float*)d_in[4];
    const float* dtw  = (const float*)d_in[5];
    const float* dtb  = (const float*)d_in[6];
    const float* alog = (const float*)d_in[7];
    const float* Dv   = (const float*)d_in[8];
    const float* ow   = (const float*)d_in[9];
    float* out = (float*)d_out;

    float *p_xz, *p_proj, *p_hend, *p_hinit, *p_sdt;
    f16 *p_xh, *p_xl, *p_xch, *p_xcl, *p_yh, *p_yl;
    f16 *p_wih, *p_wxh, *p_wxl, *p_woh;
    cudaGetSymbolAddress((void**)&p_xz, g_xz);
    cudaGetSymbolAddress((void**)&p_proj, g_proj);
    cudaGetSymbolAddress((void**)&p_hend, g_hend);
    cudaGetSymbolAddress((void**)&p_hinit, g_hinit);
    cudaGetSymbolAddress((void**)&p_sdt, g_sdt);
    cudaGetSymbolAddress((void**)&p_xh, g_xh);
    cudaGetSymbolAddress((void**)&p_xl, g_xl);
    cudaGetSymbolAddress((void**)&p_xch, g_xch);
    cudaGetSymbolAddress((void**)&p_xcl, g_xcl);
    cudaGetSymbolAddress((void**)&p_yh, g_yh);
    cudaGetSymbolAddress((void**)&p_yl, g_yl);
    cudaGetSymbolAddress((void**)&p_wih, g_wih);
    cudaGetSymbolAddress((void**)&p_wxh, g_wxh);
    cudaGetSymbolAddress((void**)&p_wxl, g_wxl);
    cudaGetSymbolAddress((void**)&p_woh, g_woh);

    cudaFuncSetAttribute((const void*)&gemm_f16s<128, 2>, cudaFuncAttributeMaxDynamicSharedMemorySize, GSM_128);
    cudaFuncSetAttribute((const void*)&gemm_f16s<64, 3>, cudaFuncAttributeMaxDynamicSharedMemorySize, GSM_64T3);
    cudaFuncSetAttribute((const void*)&scan_pass1, cudaFuncAttributeMaxDynamicSharedMemorySize, SMEM_P1);
    cudaFuncSetAttribute((const void*)&scan_pass3, cudaFuncAttributeMaxDynamicSharedMemorySize, SMEM_P3);

    // weights: in/out single fp16; x_proj split pair; input x split pair (vectorized)
    {
        int n1 = 3 * TWO_DI * DM / 4;
        cvt_kernel<<<(n1 + 255) / 256, 256>>>((const float4*)inw, (__half2*)p_wih, n1);
        int n2 = 3 * NPROJ * DI / 4;
        split_kernel<<<(n2 + 255) / 256, 256>>>((const float4*)xpw, (__half2*)p_wxh, (__half2*)p_wxl, n2);
        int n3 = 3 * DM * DI / 4;
        cvt_kernel<<<(n3 + 255) / 256, 256>>>((const float4*)ow, (__half2*)p_woh, n3);
        int n4 = ML * DM / 4;
        split_kernel<<<(n4 + 255) / 256, 256>>>((const float4*)x_in, (__half2*)p_xh, (__half2*)p_xl, n4);
    }

    for (int i = 0; i < 3; i++) {
        const f16* l_wih = p_wih + (size_t)i * TWO_DI * DM;
        const f16* l_wxh = p_wxh + (size_t)i * NPROJ * DI;
        const f16* l_wxl = p_wxl + (size_t)i * NPROJ * DI;
        const f16* l_woh = p_woh + (size_t)i * DM * DI;
        const float* l_cw   = cw   + (size_t)i * DI * 4;
        const float* l_cb   = cb   + (size_t)i * DI;
        const float* l_dtw  = dtw  + (size_t)i * DI * DTR;
        const float* l_dtb  = dtb  + (size_t)i * DI;
        const float* l_alog = alog + (size_t)i * DI * DS;
        const float* l_Dv   = Dv   + (size_t)i * DI;

        // 1. in_proj: xz = x @ inw^T   (32768 x 1120, K=280)
        gemm_f16s<128, 2><<<dim3((TWO_DI + 127) / 128, ML / 128), 256, GSM_128>>>(
            p_xh, p_xl, l_wih, nullptr, p_xz, nullptr, nullptr, TWO_DI, DM);

        // 2. causal conv + silu -> xc fp16 pair only
        conv_silu_kernel<<<dim3(L_SZ / CONV_T, B_SZ), DI>>>(p_xz, l_cw, l_cb, p_xch, p_xcl);

        // 3. x_proj: proj = xc @ xpw^T  (32768 x 50, K=560), 3-term
        gemm_f16s<64, 3><<<dim3(1, ML / 128), 256, GSM_64T3>>>(
            p_xch, p_xcl, l_wxh, l_wxl, p_proj, nullptr, nullptr, NPROJ, DI);

        // 4. selective scan (3-pass chunked, dt inline; channel-split blocks)
        {
            dim3 grid(NCH, B_SZ, 2);
            scan_pass1<<<grid, SCAN_TPB, SMEM_P1>>>(p_xch, p_xcl, p_proj, l_dtw, l_dtb,
                                                    l_alog, p_hend, p_sdt);
            int t2 = B_SZ * DI * DS;
            scan_pass2<<<(t2 + 255) / 256, 256>>>(l_alog, p_sdt, p_hend, p_hinit);
            scan_pass3<<<grid, SCAN_TPB, SMEM_P3>>>(p_xch, p_xcl, p_proj, l_dtw, l_dtb,
                                                    p_xz, l_alog, l_Dv, p_hinit, p_yh, p_yl);
        }

        // 5. out_proj: x_next = y @ ow^T  (32768 x 280, K=560)
        if (i < 2) {
            gemm_f16s<128, 2><<<dim3((DM + 127) / 128, ML / 128), 256, GSM_128>>>(
                p_yh, p_yl, l_woh, nullptr, nullptr, p_xh, p_xl, DM, DI);
        } else {
            gemm_f16s<128, 2><<<dim3((DM + 127) / 128, ML / 128), 256, GSM_128>>>(
                p_yh, p_yl, l_woh, nullptr, out, nullptr, nullptr, DM, DI);
        }
    }
}